// round 12
// baseline (speedup 1.0000x reference)
#include <cuda_runtime.h>
#include <cuda_bf16.h>
#include <cstdint>
#include <cstddef>

#define BATCH 16384
#define DG    256

// CTA tile: 64 rows. SMEM: A fragment planes (hi at 0, lo at +APLANE) +
// B ring: per-wn slots, 3 stages, 4KB each (4 ntp x (hi 512B | lo 512B)).
#define APLANE     32768
#define SA_BYTES   (2 * APLANE)                    // 65,536
#define SLOT_BYTES 4096
#define NSTAGE     3
#define SB_BYTES   (4 * NSTAGE * SLOT_BYTES)       // 49,152
#define SMEM_TOTAL (SA_BYTES + SB_BYTES)           // 114,688 -> 2 CTAs/SM (224KB)

#define NTHREADS  256
#define MTILE     64

// Packed 256x256 weight block: hi plane [kb16][p16][lane32][8 bf16], lo at +65536.
#define BLK_STRIDE 131072                          // bf16 elems per packed block

// ===========================================================================
// Global scratch (__device__ globals: allocation-free rule)
// ===========================================================================
__device__ float g_bufs[9][BATCH * DG];
__device__ float l_bufs[10][BATCH * DG];
__device__ __align__(128) __nv_bfloat16 WT_eq[BLK_STRIDE];
__device__ __align__(128) __nv_bfloat16 WT_tr[BLK_STRIDE];
__device__ __align__(128) __nv_bfloat16 WT_ab[BLK_STRIDE];
__device__ __align__(128) __nv_bfloat16 WT_ge[2 * BLK_STRIDE];   // K=512: 2 K-half blocks
__device__ __align__(128) __nv_bfloat16 WT_1 [2 * BLK_STRIDE];   // K=512: 2 K-half blocks
__device__ __align__(128) __nv_bfloat16 WT_2 [4 * BLK_STRIDE];   // N=1024: 4 N-tile blocks

__device__ __forceinline__ float sigm(float x) { return 1.0f / (1.0f + expf(-x)); }

__device__ __forceinline__ uint32_t smem_to_u32(const void* p) {
    uint32_t a;
    asm("{ .reg .u64 t; cvta.to.shared.u64 t, %1; cvt.u32.u64 %0, t; }" : "=r"(a) : "l"(p));
    return a;
}

#define CP_ASYNC16(dst_u32, src_ptr) \
    asm volatile("cp.async.cg.shared.global [%0], [%1], 16;" :: "r"(dst_u32), "l"(src_ptr))
#define CP_COMMIT() asm volatile("cp.async.commit_group;" ::: "memory")
#define CP_WAIT1()  asm volatile("cp.async.wait_group 1;" ::: "memory")
#define CP_WAIT0()  asm volatile("cp.async.wait_group 0;" ::: "memory")
#define NAMED_BAR(id) \
    asm volatile("bar.sync %0, 64;" :: "r"(id) : "memory")

#define LDS128(r0, r1, r2, r3, addr) \
    asm volatile("ld.shared.v4.b32 {%0,%1,%2,%3}, [%4];" \
        : "=r"(r0), "=r"(r1), "=r"(r2), "=r"(r3) : "r"(addr))

#define MMA16816(d, a0, a1, a2, a3, b0, b1) \
    asm volatile("mma.sync.aligned.m16n8k16.row.col.f32.bf16.bf16.f32 " \
        "{%0,%1,%2,%3}, {%4,%5,%6,%7}, {%8,%9}, {%0,%1,%2,%3};" \
        : "+f"((d)[0]), "+f"((d)[1]), "+f"((d)[2]), "+f"((d)[3]) \
        : "r"(a0), "r"(a1), "r"(a2), "r"(a3), "r"(b0), "r"(b1))

__device__ __forceinline__ void split2(float2 x, uint32_t& h, uint32_t& l) {
    __nv_bfloat162 hp = __float22bfloat162_rn(x);
    float2 hf = __bfloat1622float2(hp);
    float2 r = make_float2(x.x - hf.x, x.y - hf.y);
    __nv_bfloat162 lp = __float22bfloat162_rn(r);
    h = *reinterpret_cast<uint32_t*>(&hp);
    l = *reinterpret_cast<uint32_t*>(&lp);
}

// Write one A fragment chunk (16B hi + 16B lo) from 8 fp32 values.
__device__ __forceinline__ void write_A_frag(char* sA, int mb, int kb, int lane,
                                             float e0, float e1, float e2, float e3,
                                             float o0, float o1, float o2, float o3) {
    uint32_t h0, l0, h1, l1, h2, l2, h3, l3;
    split2(make_float2(e0, e1), h0, l0);
    split2(make_float2(e2, e3), h1, l1);
    split2(make_float2(o0, o1), h2, l2);
    split2(make_float2(o2, o3), h3, l3);
    uint32_t off = (uint32_t)((mb * 16 + kb) * 32 + lane) * 16;
    *(uint4*)(sA + off) = make_uint4(h0, h1, h2, h3);
    *(uint4*)(sA + APLANE + off) = make_uint4(l0, l1, l2, l3);
}

// ===========================================================================
// prep: pack weights into fragment-order blocks.
// ===========================================================================
__device__ __forceinline__ void pack_store(__nv_bfloat16* dst, int k, int n, float w) {
    int kb = k >> 4;
    int p = n >> 4;
    int lane = (n & 7) * 4 + ((k >> 1) & 3);
    int idx = ((n >> 3) & 1) * 4 + ((k >> 3) & 1) * 2 + (k & 1);
    size_t off = ((size_t)((kb * 16 + p) * 32 + lane)) * 8 + idx;
    __nv_bfloat16 h = __float2bfloat16(w);
    dst[off] = h;
    dst[65536 + off] = __float2bfloat16(w - __bfloat162float(h));
}

__global__ void prep_kernel(const float* __restrict__ Wge, const float* __restrict__ Weq,
                            const float* __restrict__ Wtr, const float* __restrict__ Wab,
                            const float* __restrict__ W1,  const float* __restrict__ W2) {
    int i0 = blockIdx.x * 256 + threadIdx.x;
    int stride = gridDim.x * 256;
    for (int i = i0; i < 11 * 65536; i += stride) {
        int blk = i >> 16, e = i & 65535;
        int k = e >> 8, n = e & 255;
        float w;
        __nv_bfloat16* dst;
        if (blk == 0)      { w = Weq[k * 256 + n]; dst = WT_eq; }
        else if (blk == 1) { w = Wtr[k * 256 + n]; dst = WT_tr; }
        else if (blk == 2) { w = Wab[k * 256 + n]; dst = WT_ab; }
        else if (blk <= 4) { int h = blk - 3; w = Wge[(k + h * 256) * 256 + n]; dst = WT_ge + (size_t)h * BLK_STRIDE; }
        else if (blk <= 6) { int h = blk - 5; w = W1 [(k + h * 256) * 256 + n]; dst = WT_1  + (size_t)h * BLK_STRIDE; }
        else               { int t = blk - 7; int ng = t * 256 + n;
                             w = (ng < 1000) ? W2[k * 1000 + ng] : 0.0f;
                             dst = WT_2 + (size_t)t * BLK_STRIDE; }
        pack_store(dst, k, n, w);
    }
}

// ===========================================================================
// HMMA GEMM core: acc[2][8][4] += A(frag planes) @ block^T (bf16x3 split)
// 8 warps: wm (0..1) x wn (0..3); warp tile m32 x n64. CTA tile m64 x n256.
// B: warp-PAIR cp.async ring. Pair (wm0,wn),(wm1,wn) shares slot(wn,stage);
// wm0 copies the hi plane, wm1 the lo plane. Each waits its OWN cp group,
// then a 64-thread named barrier (id 1+wn) publishes the slot — no CTA-wide
// barriers inside the K loop. Ring depth 3, prefetch distance 2 (write stage
// at kc == read stage of kc-1, separated by the pair barrier -> WAR-safe).
// CTA __syncthreads only at entry/exit (A RAW/WAR).
// ===========================================================================
__device__ __forceinline__ void hmma_gemm_k256(uint32_t sA,
                                               const __nv_bfloat16* __restrict__ blk,
                                               float acc[2][8][4],
                                               int tid, bool zero_acc) {
    if (zero_acc) {
#pragma unroll
        for (int mt = 0; mt < 2; mt++)
#pragma unroll
            for (int nt = 0; nt < 8; nt++)
#pragma unroll
                for (int i = 0; i < 4; i++) acc[mt][nt][i] = 0.f;
    }
    const int lane = tid & 31;
    const int wm = (tid >> 5) & 1, wn = tid >> 6;
    const uint32_t abase = sA + (uint32_t)(wm * 2 * 8192 + lane * 16);
    const uint32_t ring = sA + SA_BYTES + (uint32_t)wn * (NSTAGE * SLOT_BYTES);
    // producer: this warp copies plane==wm (hi for wm0 at +0, lo for wm1 at +65536)
    const __nv_bfloat16* psrc = blk + (size_t)wm * 65536 + (size_t)(wn * 4) * 256 + lane * 8;
    const uint32_t pdst = ring + (uint32_t)(wm * 512 + lane * 16);

    // Prologue: stages 0,1 <- chunks 0,1 (one commit per chunk per warp)
#pragma unroll
    for (int s = 0; s < 2; s++) {
        uint32_t dst = pdst + s * SLOT_BYTES;
        const __nv_bfloat16* src = psrc + s * 4096;
#pragma unroll
        for (int ntp = 0; ntp < 4; ntp++)
            CP_ASYNC16(dst + ntp * 1024, src + ntp * 256);
        CP_COMMIT();
    }

    __syncthreads();   // A fragments visible to all warps

    int rs = 0, ws = 2;
    for (int kc = 0; kc < 16; kc++) {
        if (kc == 15) { CP_WAIT0(); } else { CP_WAIT1(); }
        NAMED_BAR(1 + wn);     // pair barrier: publish both planes, WAR-protect ws
        if (kc + 2 < 16) {
            uint32_t dst = pdst + ws * SLOT_BYTES;
            const __nv_bfloat16* src = psrc + (size_t)(kc + 2) * 4096;
#pragma unroll
            for (int ntp = 0; ntp < 4; ntp++)
                CP_ASYNC16(dst + ntp * 1024, src + ntp * 256);
            CP_COMMIT();
        }
        uint32_t slot = ring + (uint32_t)rs * SLOT_BYTES;
        rs = (rs == NSTAGE - 1) ? 0 : rs + 1;
        ws = (ws == NSTAGE - 1) ? 0 : ws + 1;

        // A fragments
        uint32_t ah[2][4], al[2][4];
#pragma unroll
        for (int mt = 0; mt < 2; mt++) {
            uint32_t aaddr = abase + (uint32_t)(mt * 8192 + kc * 512);
            LDS128(ah[mt][0], ah[mt][1], ah[mt][2], ah[mt][3], aaddr);
            LDS128(al[mt][0], al[mt][1], al[mt][2], al[mt][3], aaddr + APLANE);
        }
        // B fragments from the pair slot
        uint32_t bh[4][4], bl[4][4];
#pragma unroll
        for (int ntp = 0; ntp < 4; ntp++) {
            uint32_t ba = slot + (uint32_t)(ntp * 1024 + lane * 16);
            LDS128(bh[ntp][0], bh[ntp][1], bh[ntp][2], bh[ntp][3], ba);
            LDS128(bl[ntp][0], bl[ntp][1], bl[ntp][2], bl[ntp][3], ba + 512);
        }
#pragma unroll
        for (int ntp = 0; ntp < 4; ntp++) {
            float* aE0 = acc[0][2 * ntp];
            float* aO0 = acc[0][2 * ntp + 1];
            float* aE1 = acc[1][2 * ntp];
            float* aO1 = acc[1][2 * ntp + 1];
            // product hh
            MMA16816(aE0, ah[0][0], ah[0][1], ah[0][2], ah[0][3], bh[ntp][0], bh[ntp][1]);
            MMA16816(aO0, ah[0][0], ah[0][1], ah[0][2], ah[0][3], bh[ntp][2], bh[ntp][3]);
            MMA16816(aE1, ah[1][0], ah[1][1], ah[1][2], ah[1][3], bh[ntp][0], bh[ntp][1]);
            MMA16816(aO1, ah[1][0], ah[1][1], ah[1][2], ah[1][3], bh[ntp][2], bh[ntp][3]);
            // product hl
            MMA16816(aE0, ah[0][0], ah[0][1], ah[0][2], ah[0][3], bl[ntp][0], bl[ntp][1]);
            MMA16816(aO0, ah[0][0], ah[0][1], ah[0][2], ah[0][3], bl[ntp][2], bl[ntp][3]);
            MMA16816(aE1, ah[1][0], ah[1][1], ah[1][2], ah[1][3], bl[ntp][0], bl[ntp][1]);
            MMA16816(aO1, ah[1][0], ah[1][1], ah[1][2], ah[1][3], bl[ntp][2], bl[ntp][3]);
            // product lh
            MMA16816(aE0, al[0][0], al[0][1], al[0][2], al[0][3], bh[ntp][0], bh[ntp][1]);
            MMA16816(aO0, al[0][0], al[0][1], al[0][2], al[0][3], bh[ntp][2], bh[ntp][3]);
            MMA16816(aE1, al[1][0], al[1][1], al[1][2], al[1][3], bh[ntp][0], bh[ntp][1]);
            MMA16816(aO1, al[1][0], al[1][1], al[1][2], al[1][3], bh[ntp][2], bh[ntp][3]);
        }
    }
    __syncthreads();   // all A reads done before caller rewrites A
}

// Fill A fragment planes (64 x 256) from row-major gmem. 256 threads.
__device__ __forceinline__ void fill_A_frag(char* sA, const float* __restrict__ src,
                                            int ld, int tid) {
#pragma unroll
    for (int i = 0; i < 8; i++) {
        int idx = i * NTHREADS + tid;           // 0..2047 = (mb*16+kb)*32+lane
        int mb = idx >> 9, kb = (idx >> 5) & 15, ln = idx & 31;
        int gid = ln >> 2, qid = ln & 3;
        const float* p0 = src + (size_t)(mb * 16 + gid) * ld + kb * 16 + 2 * qid;
        float2 x0 = *(const float2*)(p0);                 // row gid,   k low
        float2 x1 = *(const float2*)(p0 + 8 * (size_t)ld);// row gid+8, k low
        float2 x2 = *(const float2*)(p0 + 8);             // row gid,   k high
        float2 x3 = *(const float2*)(p0 + 8 * (size_t)ld + 8);
        write_A_frag(sA, mb, kb, ln, x0.x, x0.y, x1.x, x1.y, x2.x, x2.y, x3.x, x3.y);
    }
}

// Per-fragment index helper (8 warps: wm 0..1, wn 0..3)
#define FRAG_SETUP() \
    const int lane = tid & 31; \
    const int wm = (tid >> 5) & 1, wn = tid >> 6; \
    const int gid = lane >> 2, qid = lane & 3;

// ===========================================================================
// Fused plate kernel (HMMA): 64 rows per CTA, 256 threads, 2 CTAs/SM.
// ===========================================================================
template <bool DESC>
__global__ __launch_bounds__(NTHREADS, 2) void plate_hmma(
    const float* __restrict__ g_in, const float* __restrict__ l_in,
    float* __restrict__ out,
    const float* __restrict__ b_eq, const float* __restrict__ b_tr,
    const float* __restrict__ b_ab, const float* __restrict__ alpha_p) {
    extern __shared__ char sm[];
    char* sA_p = sm;
    uint32_t sA = smem_to_u32(sm);
    const int tid = threadIdx.x;
    const size_t rowbase = (size_t)blockIdx.x * MTILE;
    FRAG_SETUP();

    fill_A_frag(sA_p, l_in + rowbase * 256, 256, tid);

    float acc[2][8][4];
    // GEMM 1: l @ W_eq
    hmma_gemm_k256(sA, WT_eq, acc, tid, true);

    // Epilogue 1: df = g - sigmoid(acc + b_eq) -> A fragment planes
#pragma unroll
    for (int mt = 0; mt < 2; mt++) {
#pragma unroll
        for (int ntp = 0; ntp < 4; ntp++) {
            int ce = wn * 64 + ntp * 16 + qid * 2;
            int r = wm * 32 + mt * 16 + gid;
            size_t ro = (rowbase + r) * 256;
            float2 beE = *(const float2*)(b_eq + ce);
            float2 beO = *(const float2*)(b_eq + ce + 8);
            float2 gE0 = *(const float2*)(g_in + ro + ce);
            float2 gE1 = *(const float2*)(g_in + ro + 8 * 256 + ce);
            float2 gO0 = *(const float2*)(g_in + ro + ce + 8);
            float2 gO1 = *(const float2*)(g_in + ro + 8 * 256 + ce + 8);
            const float* aE = acc[mt][2 * ntp];
            const float* aO = acc[mt][2 * ntp + 1];
            write_A_frag(sA_p, wm * 2 + mt, wn * 4 + ntp, lane,
                         gE0.x - sigm(aE[0] + beE.x), gE0.y - sigm(aE[1] + beE.y),
                         gE1.x - sigm(aE[2] + beE.x), gE1.y - sigm(aE[3] + beE.y),
                         gO0.x - sigm(aO[0] + beO.x), gO0.y - sigm(aO[1] + beO.y),
                         gO1.x - sigm(aO[2] + beO.x), gO1.y - sigm(aO[3] + beO.y));
        }
    }

    // GEMM 2: df @ W_tr
    hmma_gemm_k256(sA, WT_tr, acc, tid, true);

    const float alpha = *alpha_p;

    if (!DESC) {
        // out = g - alpha*(acc + b_tr)
#pragma unroll
        for (int mt = 0; mt < 2; mt++) {
#pragma unroll
            for (int nt = 0; nt < 8; nt++) {
                int col = wn * 64 + nt * 8 + qid * 2;
                int r = wm * 32 + mt * 16 + gid;
                size_t ro = (rowbase + r) * 256 + col;
                float2 bt = *(const float2*)(b_tr + col);
                float2 g0 = *(const float2*)(g_in + ro);
                float2 g1 = *(const float2*)(g_in + ro + 8 * 256);
                float2 o0, o1;
                o0.x = g0.x - alpha * (acc[mt][nt][0] + bt.x);
                o0.y = g0.y - alpha * (acc[mt][nt][1] + bt.y);
                o1.x = g1.x - alpha * (acc[mt][nt][2] + bt.x);
                o1.y = g1.y - alpha * (acc[mt][nt][3] + bt.y);
                *(float2*)(out + ro) = o0;
                *(float2*)(out + ro + 8 * 256) = o1;
            }
        }
    } else {
        // delta = alpha*(acc + b_tr) -> A fragment planes
#pragma unroll
        for (int mt = 0; mt < 2; mt++) {
#pragma unroll
            for (int ntp = 0; ntp < 4; ntp++) {
                int ce = wn * 64 + ntp * 16 + qid * 2;
                float2 btE = *(const float2*)(b_tr + ce);
                float2 btO = *(const float2*)(b_tr + ce + 8);
                const float* aE = acc[mt][2 * ntp];
                const float* aO = acc[mt][2 * ntp + 1];
                write_A_frag(sA_p, wm * 2 + mt, wn * 4 + ntp, lane,
                             alpha * (aE[0] + btE.x), alpha * (aE[1] + btE.y),
                             alpha * (aE[2] + btE.x), alpha * (aE[3] + btE.y),
                             alpha * (aO[0] + btO.x), alpha * (aO[1] + btO.y),
                             alpha * (aO[2] + btO.x), alpha * (aO[3] + btO.y));
            }
        }

        // GEMM 3: delta @ W_ab
        hmma_gemm_k256(sA, WT_ab, acc, tid, true);

        // out = l + acc + b_ab
#pragma unroll
        for (int mt = 0; mt < 2; mt++) {
#pragma unroll
            for (int nt = 0; nt < 8; nt++) {
                int col = wn * 64 + nt * 8 + qid * 2;
                int r = wm * 32 + mt * 16 + gid;
                size_t ro = (rowbase + r) * 256 + col;
                float2 ba = *(const float2*)(b_ab + col);
                float2 l0 = *(const float2*)(l_in + ro);
                float2 l1 = *(const float2*)(l_in + ro + 8 * 256);
                float2 o0, o1;
                o0.x = l0.x + acc[mt][nt][0] + ba.x;
                o0.y = l0.y + acc[mt][nt][1] + ba.y;
                o1.x = l1.x + acc[mt][nt][2] + ba.x;
                o1.y = l1.y + acc[mt][nt][3] + ba.y;
                *(float2*)(out + ro) = o0;
                *(float2*)(out + ro + 8 * 256) = o1;
            }
        }
    }
}

// ===========================================================================
// Encoder: g0 = relu(x @ W_ge + b_ge), K = 512 as two accumulated K=256 passes
// ===========================================================================
__global__ __launch_bounds__(NTHREADS, 2) void encoder_hmma(
    const float* __restrict__ x, const float* __restrict__ b_ge,
    float* __restrict__ g0) {
    extern __shared__ char sm[];
    char* sA_p = sm;
    uint32_t sA = smem_to_u32(sm);
    const int tid = threadIdx.x;
    const size_t rowbase = (size_t)blockIdx.x * MTILE;
    FRAG_SETUP();

    float acc[2][8][4];
    fill_A_frag(sA_p, x + rowbase * 512, 512, tid);
    hmma_gemm_k256(sA, WT_ge, acc, tid, true);
    fill_A_frag(sA_p, x + rowbase * 512 + 256, 512, tid);
    hmma_gemm_k256(sA, WT_ge + BLK_STRIDE, acc, tid, false);

#pragma unroll
    for (int mt = 0; mt < 2; mt++) {
#pragma unroll
        for (int nt = 0; nt < 8; nt++) {
            int col = wn * 64 + nt * 8 + qid * 2;
            int r = wm * 32 + mt * 16 + gid;
            size_t ro = (rowbase + r) * 256 + col;
            float2 b = *(const float2*)(b_ge + col);
            float2 o0, o1;
            o0.x = fmaxf(acc[mt][nt][0] + b.x, 0.f);
            o0.y = fmaxf(acc[mt][nt][1] + b.y, 0.f);
            o1.x = fmaxf(acc[mt][nt][2] + b.x, 0.f);
            o1.y = fmaxf(acc[mt][nt][3] + b.y, 0.f);
            *(float2*)(g0 + ro) = o0;
            *(float2*)(g0 + ro + 8 * 256) = o1;
        }
    }
}

// ===========================================================================
// Head: h = relu([g8||l1] @ W1 + b1); out = h @ W2 + b2  (N=1000, 4 tiles)
// ===========================================================================
__global__ __launch_bounds__(NTHREADS, 2) void head_hmma(
    const float* __restrict__ g8, const float* __restrict__ l1,
    const float* __restrict__ b1, const float* __restrict__ b2,
    float* __restrict__ out) {
    extern __shared__ char sm[];
    char* sA_p = sm;
    uint32_t sA = smem_to_u32(sm);
    const int tid = threadIdx.x;
    const size_t rowbase = (size_t)blockIdx.x * MTILE;
    FRAG_SETUP();

    float acc[2][8][4];
    fill_A_frag(sA_p, g8 + rowbase * 256, 256, tid);
    hmma_gemm_k256(sA, WT_1, acc, tid, true);
    fill_A_frag(sA_p, l1 + rowbase * 256, 256, tid);
    hmma_gemm_k256(sA, WT_1 + BLK_STRIDE, acc, tid, false);

    // h = relu(acc + b1) -> A fragment planes
#pragma unroll
    for (int mt = 0; mt < 2; mt++) {
#pragma unroll
        for (int ntp = 0; ntp < 4; ntp++) {
            int ce = wn * 64 + ntp * 16 + qid * 2;
            float2 bE = *(const float2*)(b1 + ce);
            float2 bO = *(const float2*)(b1 + ce + 8);
            const float* aE = acc[mt][2 * ntp];
            const float* aO = acc[mt][2 * ntp + 1];
            write_A_frag(sA_p, wm * 2 + mt, wn * 4 + ntp, lane,
                         fmaxf(aE[0] + bE.x, 0.f), fmaxf(aE[1] + bE.y, 0.f),
                         fmaxf(aE[2] + bE.x, 0.f), fmaxf(aE[3] + bE.y, 0.f),
                         fmaxf(aO[0] + bO.x, 0.f), fmaxf(aO[1] + bO.y, 0.f),
                         fmaxf(aO[2] + bO.x, 0.f), fmaxf(aO[3] + bO.y, 0.f));
        }
    }

    for (int t = 0; t < 4; t++) {
        hmma_gemm_k256(sA, WT_2 + (size_t)t * BLK_STRIDE, acc, tid, true);
#pragma unroll
        for (int mt = 0; mt < 2; mt++) {
#pragma unroll
            for (int nt = 0; nt < 8; nt++) {
                int col = t * 256 + wn * 64 + nt * 8 + qid * 2;
                if (col < 1000) {
                    int r = wm * 32 + mt * 16 + gid;
                    size_t ro = (rowbase + r) * 1000 + col;
                    float2 b = *(const float2*)(b2 + col);
                    float2 o0, o1;
                    o0.x = acc[mt][nt][0] + b.x;
                    o0.y = acc[mt][nt][1] + b.y;
                    o1.x = acc[mt][nt][2] + b.x;
                    o1.y = acc[mt][nt][3] + b.y;
                    *(float2*)(out + ro) = o0;
                    *(float2*)(out + ro + 8 * 1000) = o1;
                }
            }
        }
    }
}

// ===========================================================================
extern "C" void kernel_launch(void* const* d_in, const int* in_sizes, int n_in,
                              void* d_out, int out_size) {
    (void)in_sizes; (void)n_in; (void)out_size;
    const float* x     = (const float*)d_in[0];
    const float* W_ge  = (const float*)d_in[1];
    const float* b_ge  = (const float*)d_in[2];
    const float* W_eq  = (const float*)d_in[3];
    const float* b_eq  = (const float*)d_in[4];
    const float* W_tr  = (const float*)d_in[5];
    const float* b_tr  = (const float*)d_in[6];
    const float* W_ab  = (const float*)d_in[7];
    const float* b_ab  = (const float*)d_in[8];
    const float* alpha = (const float*)d_in[9];
    const float* W1    = (const float*)d_in[10];
    const float* b1    = (const float*)d_in[11];
    const float* W2    = (const float*)d_in[12];
    const float* b2    = (const float*)d_in[13];
    float* out = (float*)d_out;

    float *gb = nullptr, *lb = nullptr;
    cudaGetSymbolAddress((void**)&gb, g_bufs);
    cudaGetSymbolAddress((void**)&lb, l_bufs);
    auto G = [&](int i) { return gb + (size_t)i * BATCH * DG; };
    auto L = [&](int i) { return lb + (size_t)i * BATCH * DG; };

    cudaFuncSetAttribute(plate_hmma<true>,  cudaFuncAttributeMaxDynamicSharedMemorySize, SMEM_TOTAL);
    cudaFuncSetAttribute(plate_hmma<false>, cudaFuncAttributeMaxDynamicSharedMemorySize, SMEM_TOTAL);
    cudaFuncSetAttribute(encoder_hmma,      cudaFuncAttributeMaxDynamicSharedMemorySize, SMEM_TOTAL);
    cudaFuncSetAttribute(head_hmma,         cudaFuncAttributeMaxDynamicSharedMemorySize, SMEM_TOTAL);

    cudaMemsetAsync(L(9), 0, (size_t)BATCH * DG * sizeof(float));
    prep_kernel<<<512, 256>>>(W_ge, W_eq, W_tr, W_ab, W1, W2);

    dim3 grid(BATCH / MTILE);   // 256 CTAs, 2 CTAs/SM

    encoder_hmma<<<grid, NTHREADS, SMEM_TOTAL>>>(x, b_ge, G(0));

    // Sweep 1: descending (g[1..8] None -> g_in = g0)
    for (int n = 8; n >= 1; --n)
        plate_hmma<true><<<grid, NTHREADS, SMEM_TOTAL>>>(G(0), L(n + 1), L(n),
                                                         b_eq, b_tr, b_ab, alpha);
    // Sweep 1: ascending
    for (int n = 1; n <= 8; ++n)
        plate_hmma<false><<<grid, NTHREADS, SMEM_TOTAL>>>(G(n - 1), L(n), G(n),
                                                          b_eq, b_tr, b_ab, alpha);
    // Sweep 2: descending
    for (int n = 8; n >= 1; --n)
        plate_hmma<true><<<grid, NTHREADS, SMEM_TOTAL>>>(G(n - 1), L(n + 1), L(n),
                                                         b_eq, b_tr, b_ab, alpha);
    // Sweep 2: ascending
    for (int n = 1; n <= 8; ++n)
        plate_hmma<false><<<grid, NTHREADS, SMEM_TOTAL>>>(G(n - 1), L(n), G(n),
                                                          b_eq, b_tr, b_ab, alpha);

    head_hmma<<<grid, NTHREADS, SMEM_TOTAL>>>(G(8), L(1), b1, b2, out);
}

// round 13
// speedup vs baseline: 1.0982x; 1.0982x over previous
#include <cuda_runtime.h>
#include <cuda_bf16.h>
#include <cstdint>
#include <cstddef>

#define BATCH 16384
#define DG    256

// CTA tile: 64 rows. SMEM: A fragment planes only (hi at 0, lo at +APLANE).
// Chunk(mb 0..3, kb 0..15, lane 0..31) = 16B m16k16 A fragment.
#define APLANE    32768
#define SA_BYTES  (2 * APLANE)                     // 65,536 -> 2 CTAs/SM
#define SMEM_TOTAL SA_BYTES

#define NTHREADS  256
#define MTILE     64

// Packed 256x256 weight block: hi plane [kb16][p16][lane32][8 bf16], lo at +65536.
#define BLK_STRIDE 131072                          // bf16 elems per packed block

// ===========================================================================
// Global scratch (__device__ globals: allocation-free rule)
// ===========================================================================
__device__ float g_bufs[9][BATCH * DG];
__device__ float l_bufs[10][BATCH * DG];
__device__ __align__(128) __nv_bfloat16 WT_eq[BLK_STRIDE];
__device__ __align__(128) __nv_bfloat16 WT_tr[BLK_STRIDE];
__device__ __align__(128) __nv_bfloat16 WT_ab[BLK_STRIDE];
__device__ __align__(128) __nv_bfloat16 WT_ge[2 * BLK_STRIDE];   // K=512: 2 K-half blocks
__device__ __align__(128) __nv_bfloat16 WT_1 [2 * BLK_STRIDE];   // K=512: 2 K-half blocks
__device__ __align__(128) __nv_bfloat16 WT_2 [4 * BLK_STRIDE];   // N=1024: 4 N-tile blocks

__device__ __forceinline__ float sigm(float x) { return 1.0f / (1.0f + expf(-x)); }

__device__ __forceinline__ uint32_t smem_to_u32(const void* p) {
    uint32_t a;
    asm("{ .reg .u64 t; cvta.to.shared.u64 t, %1; cvt.u32.u64 %0, t; }" : "=r"(a) : "l"(p));
    return a;
}

#define LDS128(r0, r1, r2, r3, addr) \
    asm volatile("ld.shared.v4.b32 {%0,%1,%2,%3}, [%4];" \
        : "=r"(r0), "=r"(r1), "=r"(r2), "=r"(r3) : "r"(addr))

#define LDG128(r0, r1, r2, r3, ptr) \
    asm volatile("ld.global.nc.v4.u32 {%0,%1,%2,%3}, [%4];" \
        : "=r"(r0), "=r"(r1), "=r"(r2), "=r"(r3) : "l"(ptr))

#define MMA16816(d, a0, a1, a2, a3, b0, b1) \
    asm volatile("mma.sync.aligned.m16n8k16.row.col.f32.bf16.bf16.f32 " \
        "{%0,%1,%2,%3}, {%4,%5,%6,%7}, {%8,%9}, {%0,%1,%2,%3};" \
        : "+f"((d)[0]), "+f"((d)[1]), "+f"((d)[2]), "+f"((d)[3]) \
        : "r"(a0), "r"(a1), "r"(a2), "r"(a3), "r"(b0), "r"(b1))

__device__ __forceinline__ void split2(float2 x, uint32_t& h, uint32_t& l) {
    __nv_bfloat162 hp = __float22bfloat162_rn(x);
    float2 hf = __bfloat1622float2(hp);
    float2 r = make_float2(x.x - hf.x, x.y - hf.y);
    __nv_bfloat162 lp = __float22bfloat162_rn(r);
    h = *reinterpret_cast<uint32_t*>(&hp);
    l = *reinterpret_cast<uint32_t*>(&lp);
}

// Write one A fragment chunk (16B hi + 16B lo) from 8 fp32 values.
__device__ __forceinline__ void write_A_frag(char* sA, int mb, int kb, int lane,
                                             float e0, float e1, float e2, float e3,
                                             float o0, float o1, float o2, float o3) {
    uint32_t h0, l0, h1, l1, h2, l2, h3, l3;
    split2(make_float2(e0, e1), h0, l0);
    split2(make_float2(e2, e3), h1, l1);
    split2(make_float2(o0, o1), h2, l2);
    split2(make_float2(o2, o3), h3, l3);
    uint32_t off = (uint32_t)((mb * 16 + kb) * 32 + lane) * 16;
    *(uint4*)(sA + off) = make_uint4(h0, h1, h2, h3);
    *(uint4*)(sA + APLANE + off) = make_uint4(l0, l1, l2, l3);
}

// ===========================================================================
// prep: pack weights into fragment-order blocks.
// ===========================================================================
__device__ __forceinline__ void pack_store(__nv_bfloat16* dst, int k, int n, float w) {
    int kb = k >> 4;
    int p = n >> 4;
    int lane = (n & 7) * 4 + ((k >> 1) & 3);
    int idx = ((n >> 3) & 1) * 4 + ((k >> 3) & 1) * 2 + (k & 1);
    size_t off = ((size_t)((kb * 16 + p) * 32 + lane)) * 8 + idx;
    __nv_bfloat16 h = __float2bfloat16(w);
    dst[off] = h;
    dst[65536 + off] = __float2bfloat16(w - __bfloat162float(h));
}

__global__ void prep_kernel(const float* __restrict__ Wge, const float* __restrict__ Weq,
                            const float* __restrict__ Wtr, const float* __restrict__ Wab,
                            const float* __restrict__ W1,  const float* __restrict__ W2) {
    int i0 = blockIdx.x * 256 + threadIdx.x;
    int stride = gridDim.x * 256;
    for (int i = i0; i < 11 * 65536; i += stride) {
        int blk = i >> 16, e = i & 65535;
        int k = e >> 8, n = e & 255;
        float w;
        __nv_bfloat16* dst;
        if (blk == 0)      { w = Weq[k * 256 + n]; dst = WT_eq; }
        else if (blk == 1) { w = Wtr[k * 256 + n]; dst = WT_tr; }
        else if (blk == 2) { w = Wab[k * 256 + n]; dst = WT_ab; }
        else if (blk <= 4) { int h = blk - 3; w = Wge[(k + h * 256) * 256 + n]; dst = WT_ge + (size_t)h * BLK_STRIDE; }
        else if (blk <= 6) { int h = blk - 5; w = W1 [(k + h * 256) * 256 + n]; dst = WT_1  + (size_t)h * BLK_STRIDE; }
        else               { int t = blk - 7; int ng = t * 256 + n;
                             w = (ng < 1000) ? W2[k * 1000 + ng] : 0.0f;
                             dst = WT_2 + (size_t)t * BLK_STRIDE; }
        pack_store(dst, k, n, w);
    }
}

// ===========================================================================
// HMMA GEMM core: acc[4][4][4] += A(frag planes) @ block^T (bf16x3 split)
// 8 warps, wn = warp id (0..7); warp tile m64 x n32 (p = wn*2, wn*2+1).
// B fragments LDG'd straight from gmem, REGISTER double-buffered across kc:
// chunk kc+1's 4 LDG.128 issue before kc's 48-MMA block (latency hidden, no
// barriers). Each warp's B is unique (no duplicate loads). A via LDS.128,
// one mt-pair (16 regs) live at a time.
// __syncthreads at entry (A RAW) and exit (A WAR) only.
// ===========================================================================
__device__ __forceinline__ void hmma_gemm_k256(uint32_t sA,
                                               const __nv_bfloat16* __restrict__ blk,
                                               float acc[4][4][4],
                                               int tid, bool zero_acc) {
    if (zero_acc) {
#pragma unroll
        for (int mt = 0; mt < 4; mt++)
#pragma unroll
            for (int nt = 0; nt < 4; nt++)
#pragma unroll
                for (int i = 0; i < 4; i++) acc[mt][nt][i] = 0.f;
    }
    const int lane = tid & 31;
    const int wn = tid >> 5;
    const uint32_t abase = sA + (uint32_t)(lane * 16);
    // B base: p = wn*2 + pp; elem offset ((kc*16 + p)*32 + lane)*8
    const __nv_bfloat16* bbase = blk + ((size_t)(wn * 2) * 32 + lane) * 8;

    uint32_t bh[2][2][4], bl[2][2][4];   // [buf][pp][reg]
    // Prologue: chunk 0 -> buf 0
#pragma unroll
    for (int pp = 0; pp < 2; pp++) {
        const __nv_bfloat16* bp = bbase + pp * 256;
        LDG128(bh[0][pp][0], bh[0][pp][1], bh[0][pp][2], bh[0][pp][3], bp);
        LDG128(bl[0][pp][0], bl[0][pp][1], bl[0][pp][2], bl[0][pp][3], bp + 65536);
    }

    __syncthreads();   // A fragments visible

#pragma unroll 2
    for (int kc = 0; kc < 16; kc++) {
        const int cur = kc & 1, nxt = cur ^ 1;
        if (kc < 15) {
            const __nv_bfloat16* bk = bbase + (size_t)(kc + 1) * 4096;
#pragma unroll
            for (int pp = 0; pp < 2; pp++) {
                const __nv_bfloat16* bp = bk + pp * 256;
                LDG128(bh[nxt][pp][0], bh[nxt][pp][1], bh[nxt][pp][2], bh[nxt][pp][3], bp);
                LDG128(bl[nxt][pp][0], bl[nxt][pp][1], bl[nxt][pp][2], bl[nxt][pp][3], bp + 65536);
            }
        }
#pragma unroll
        for (int mpair = 0; mpair < 2; mpair++) {
            uint32_t ah[2][4], al[2][4];
#pragma unroll
            for (int m2 = 0; m2 < 2; m2++) {
                uint32_t aaddr = abase + (uint32_t)((mpair * 2 + m2) * 8192 + kc * 512);
                LDS128(ah[m2][0], ah[m2][1], ah[m2][2], ah[m2][3], aaddr);
                LDS128(al[m2][0], al[m2][1], al[m2][2], al[m2][3], aaddr + APLANE);
            }
#pragma unroll
            for (int pp = 0; pp < 2; pp++) {
#pragma unroll
                for (int m2 = 0; m2 < 2; m2++) {
                    const int mt = mpair * 2 + m2;
                    float* aE = acc[mt][2 * pp];
                    float* aO = acc[mt][2 * pp + 1];
                    MMA16816(aE, ah[m2][0], ah[m2][1], ah[m2][2], ah[m2][3],
                             bh[cur][pp][0], bh[cur][pp][1]);
                    MMA16816(aO, ah[m2][0], ah[m2][1], ah[m2][2], ah[m2][3],
                             bh[cur][pp][2], bh[cur][pp][3]);
                    MMA16816(aE, ah[m2][0], ah[m2][1], ah[m2][2], ah[m2][3],
                             bl[cur][pp][0], bl[cur][pp][1]);
                    MMA16816(aO, ah[m2][0], ah[m2][1], ah[m2][2], ah[m2][3],
                             bl[cur][pp][2], bl[cur][pp][3]);
                    MMA16816(aE, al[m2][0], al[m2][1], al[m2][2], al[m2][3],
                             bh[cur][pp][0], bh[cur][pp][1]);
                    MMA16816(aO, al[m2][0], al[m2][1], al[m2][2], al[m2][3],
                             bh[cur][pp][2], bh[cur][pp][3]);
                }
            }
        }
    }
    __syncthreads();   // all A reads done before caller rewrites A
}

// Fill A fragment planes (64 x 256) from row-major gmem. 256 threads.
__device__ __forceinline__ void fill_A_frag(char* sA, const float* __restrict__ src,
                                            int ld, int tid) {
#pragma unroll
    for (int i = 0; i < 8; i++) {
        int idx = i * NTHREADS + tid;           // 0..2047 = (mb*16+kb)*32+lane
        int mb = idx >> 9, kb = (idx >> 5) & 15, ln = idx & 31;
        int gid = ln >> 2, qid = ln & 3;
        const float* p0 = src + (size_t)(mb * 16 + gid) * ld + kb * 16 + 2 * qid;
        float2 x0 = *(const float2*)(p0);                 // row gid,   k low
        float2 x1 = *(const float2*)(p0 + 8 * (size_t)ld);// row gid+8, k low
        float2 x2 = *(const float2*)(p0 + 8);             // row gid,   k high
        float2 x3 = *(const float2*)(p0 + 8 * (size_t)ld + 8);
        write_A_frag(sA, mb, kb, ln, x0.x, x0.y, x1.x, x1.y, x2.x, x2.y, x3.x, x3.y);
    }
}

// Per-fragment index helper (8 warps: wn 0..7, warp tile m64 x n32)
#define FRAG_SETUP() \
    const int lane = tid & 31; \
    const int wn = tid >> 5; \
    const int gid = lane >> 2, qid = lane & 3;

// acc[mt][nt]: rows mt*16+gid (+8), cols wn*32 + (nt>>1)*16 + (nt&1)*8 + qid*2

// ===========================================================================
// Fused plate kernel (HMMA): 64 rows per CTA, 256 threads, 2 CTAs/SM.
// ===========================================================================
template <bool DESC>
__global__ __launch_bounds__(NTHREADS, 2) void plate_hmma(
    const float* __restrict__ g_in, const float* __restrict__ l_in,
    float* __restrict__ out,
    const float* __restrict__ b_eq, const float* __restrict__ b_tr,
    const float* __restrict__ b_ab, const float* __restrict__ alpha_p) {
    extern __shared__ char sm[];
    char* sA_p = sm;
    uint32_t sA = smem_to_u32(sm);
    const int tid = threadIdx.x;
    const size_t rowbase = (size_t)blockIdx.x * MTILE;
    FRAG_SETUP();

    fill_A_frag(sA_p, l_in + rowbase * 256, 256, tid);

    float acc[4][4][4];
    // GEMM 1: l @ W_eq
    hmma_gemm_k256(sA, WT_eq, acc, tid, true);

    // Epilogue 1: df = g - sigmoid(acc + b_eq) -> A fragment planes
#pragma unroll
    for (int mt = 0; mt < 4; mt++) {
#pragma unroll
        for (int ntp = 0; ntp < 2; ntp++) {
            int ce = wn * 32 + ntp * 16 + qid * 2;
            int r = mt * 16 + gid;
            size_t ro = (rowbase + r) * 256;
            float2 beE = *(const float2*)(b_eq + ce);
            float2 beO = *(const float2*)(b_eq + ce + 8);
            float2 gE0 = *(const float2*)(g_in + ro + ce);
            float2 gE1 = *(const float2*)(g_in + ro + 8 * 256 + ce);
            float2 gO0 = *(const float2*)(g_in + ro + ce + 8);
            float2 gO1 = *(const float2*)(g_in + ro + 8 * 256 + ce + 8);
            const float* aE = acc[mt][2 * ntp];
            const float* aO = acc[mt][2 * ntp + 1];
            write_A_frag(sA_p, mt, wn * 2 + ntp, lane,
                         gE0.x - sigm(aE[0] + beE.x), gE0.y - sigm(aE[1] + beE.y),
                         gE1.x - sigm(aE[2] + beE.x), gE1.y - sigm(aE[3] + beE.y),
                         gO0.x - sigm(aO[0] + beO.x), gO0.y - sigm(aO[1] + beO.y),
                         gO1.x - sigm(aO[2] + beO.x), gO1.y - sigm(aO[3] + beO.y));
        }
    }

    // GEMM 2: df @ W_tr
    hmma_gemm_k256(sA, WT_tr, acc, tid, true);

    const float alpha = *alpha_p;

    if (!DESC) {
        // out = g - alpha*(acc + b_tr)
#pragma unroll
        for (int mt = 0; mt < 4; mt++) {
#pragma unroll
            for (int nt = 0; nt < 4; nt++) {
                int col = wn * 32 + (nt >> 1) * 16 + (nt & 1) * 8 + qid * 2;
                int r = mt * 16 + gid;
                size_t ro = (rowbase + r) * 256 + col;
                float2 bt = *(const float2*)(b_tr + col);
                float2 g0 = *(const float2*)(g_in + ro);
                float2 g1 = *(const float2*)(g_in + ro + 8 * 256);
                float2 o0, o1;
                o0.x = g0.x - alpha * (acc[mt][nt][0] + bt.x);
                o0.y = g0.y - alpha * (acc[mt][nt][1] + bt.y);
                o1.x = g1.x - alpha * (acc[mt][nt][2] + bt.x);
                o1.y = g1.y - alpha * (acc[mt][nt][3] + bt.y);
                *(float2*)(out + ro) = o0;
                *(float2*)(out + ro + 8 * 256) = o1;
            }
        }
    } else {
        // delta = alpha*(acc + b_tr) -> A fragment planes
#pragma unroll
        for (int mt = 0; mt < 4; mt++) {
#pragma unroll
            for (int ntp = 0; ntp < 2; ntp++) {
                int ce = wn * 32 + ntp * 16 + qid * 2;
                float2 btE = *(const float2*)(b_tr + ce);
                float2 btO = *(const float2*)(b_tr + ce + 8);
                const float* aE = acc[mt][2 * ntp];
                const float* aO = acc[mt][2 * ntp + 1];
                write_A_frag(sA_p, mt, wn * 2 + ntp, lane,
                             alpha * (aE[0] + btE.x), alpha * (aE[1] + btE.y),
                             alpha * (aE[2] + btE.x), alpha * (aE[3] + btE.y),
                             alpha * (aO[0] + btO.x), alpha * (aO[1] + btO.y),
                             alpha * (aO[2] + btO.x), alpha * (aO[3] + btO.y));
            }
        }

        // GEMM 3: delta @ W_ab
        hmma_gemm_k256(sA, WT_ab, acc, tid, true);

        // out = l + acc + b_ab
#pragma unroll
        for (int mt = 0; mt < 4; mt++) {
#pragma unroll
            for (int nt = 0; nt < 4; nt++) {
                int col = wn * 32 + (nt >> 1) * 16 + (nt & 1) * 8 + qid * 2;
                int r = mt * 16 + gid;
                size_t ro = (rowbase + r) * 256 + col;
                float2 ba = *(const float2*)(b_ab + col);
                float2 l0 = *(const float2*)(l_in + ro);
                float2 l1 = *(const float2*)(l_in + ro + 8 * 256);
                float2 o0, o1;
                o0.x = l0.x + acc[mt][nt][0] + ba.x;
                o0.y = l0.y + acc[mt][nt][1] + ba.y;
                o1.x = l1.x + acc[mt][nt][2] + ba.x;
                o1.y = l1.y + acc[mt][nt][3] + ba.y;
                *(float2*)(out + ro) = o0;
                *(float2*)(out + ro + 8 * 256) = o1;
            }
        }
    }
}

// ===========================================================================
// Encoder: g0 = relu(x @ W_ge + b_ge), K = 512 as two accumulated K=256 passes
// ===========================================================================
__global__ __launch_bounds__(NTHREADS, 2) void encoder_hmma(
    const float* __restrict__ x, const float* __restrict__ b_ge,
    float* __restrict__ g0) {
    extern __shared__ char sm[];
    char* sA_p = sm;
    uint32_t sA = smem_to_u32(sm);
    const int tid = threadIdx.x;
    const size_t rowbase = (size_t)blockIdx.x * MTILE;
    FRAG_SETUP();

    float acc[4][4][4];
    fill_A_frag(sA_p, x + rowbase * 512, 512, tid);
    hmma_gemm_k256(sA, WT_ge, acc, tid, true);
    fill_A_frag(sA_p, x + rowbase * 512 + 256, 512, tid);
    hmma_gemm_k256(sA, WT_ge + BLK_STRIDE, acc, tid, false);

#pragma unroll
    for (int mt = 0; mt < 4; mt++) {
#pragma unroll
        for (int nt = 0; nt < 4; nt++) {
            int col = wn * 32 + (nt >> 1) * 16 + (nt & 1) * 8 + qid * 2;
            int r = mt * 16 + gid;
            size_t ro = (rowbase + r) * 256 + col;
            float2 b = *(const float2*)(b_ge + col);
            float2 o0, o1;
            o0.x = fmaxf(acc[mt][nt][0] + b.x, 0.f);
            o0.y = fmaxf(acc[mt][nt][1] + b.y, 0.f);
            o1.x = fmaxf(acc[mt][nt][2] + b.x, 0.f);
            o1.y = fmaxf(acc[mt][nt][3] + b.y, 0.f);
            *(float2*)(g0 + ro) = o0;
            *(float2*)(g0 + ro + 8 * 256) = o1;
        }
    }
}

// ===========================================================================
// Head: h = relu([g8||l1] @ W1 + b1); out = h @ W2 + b2  (N=1000, 4 tiles)
// ===========================================================================
__global__ __launch_bounds__(NTHREADS, 2) void head_hmma(
    const float* __restrict__ g8, const float* __restrict__ l1,
    const float* __restrict__ b1, const float* __restrict__ b2,
    float* __restrict__ out) {
    extern __shared__ char sm[];
    char* sA_p = sm;
    uint32_t sA = smem_to_u32(sm);
    const int tid = threadIdx.x;
    const size_t rowbase = (size_t)blockIdx.x * MTILE;
    FRAG_SETUP();

    float acc[4][4][4];
    fill_A_frag(sA_p, g8 + rowbase * 256, 256, tid);
    hmma_gemm_k256(sA, WT_1, acc, tid, true);
    fill_A_frag(sA_p, l1 + rowbase * 256, 256, tid);
    hmma_gemm_k256(sA, WT_1 + BLK_STRIDE, acc, tid, false);

    // h = relu(acc + b1) -> A fragment planes
#pragma unroll
    for (int mt = 0; mt < 4; mt++) {
#pragma unroll
        for (int ntp = 0; ntp < 2; ntp++) {
            int ce = wn * 32 + ntp * 16 + qid * 2;
            float2 bE = *(const float2*)(b1 + ce);
            float2 bO = *(const float2*)(b1 + ce + 8);
            const float* aE = acc[mt][2 * ntp];
            const float* aO = acc[mt][2 * ntp + 1];
            write_A_frag(sA_p, mt, wn * 2 + ntp, lane,
                         fmaxf(aE[0] + bE.x, 0.f), fmaxf(aE[1] + bE.y, 0.f),
                         fmaxf(aE[2] + bE.x, 0.f), fmaxf(aE[3] + bE.y, 0.f),
                         fmaxf(aO[0] + bO.x, 0.f), fmaxf(aO[1] + bO.y, 0.f),
                         fmaxf(aO[2] + bO.x, 0.f), fmaxf(aO[3] + bO.y, 0.f));
        }
    }

    for (int t = 0; t < 4; t++) {
        hmma_gemm_k256(sA, WT_2 + (size_t)t * BLK_STRIDE, acc, tid, true);
#pragma unroll
        for (int mt = 0; mt < 4; mt++) {
#pragma unroll
            for (int nt = 0; nt < 4; nt++) {
                int col = t * 256 + wn * 32 + (nt >> 1) * 16 + (nt & 1) * 8 + qid * 2;
                if (col < 1000) {
                    int r = mt * 16 + gid;
                    size_t ro = (rowbase + r) * 1000 + col;
                    float2 b = *(const float2*)(b2 + col);
                    float2 o0, o1;
                    o0.x = acc[mt][nt][0] + b.x;
                    o0.y = acc[mt][nt][1] + b.y;
                    o1.x = acc[mt][nt][2] + b.x;
                    o1.y = acc[mt][nt][3] + b.y;
                    *(float2*)(out + ro) = o0;
                    *(float2*)(out + ro + 8 * 1000) = o1;
                }
            }
        }
    }
}

// ===========================================================================
extern "C" void kernel_launch(void* const* d_in, const int* in_sizes, int n_in,
                              void* d_out, int out_size) {
    (void)in_sizes; (void)n_in; (void)out_size;
    const float* x     = (const float*)d_in[0];
    const float* W_ge  = (const float*)d_in[1];
    const float* b_ge  = (const float*)d_in[2];
    const float* W_eq  = (const float*)d_in[3];
    const float* b_eq  = (const float*)d_in[4];
    const float* W_tr  = (const float*)d_in[5];
    const float* b_tr  = (const float*)d_in[6];
    const float* W_ab  = (const float*)d_in[7];
    const float* b_ab  = (const float*)d_in[8];
    const float* alpha = (const float*)d_in[9];
    const float* W1    = (const float*)d_in[10];
    const float* b1    = (const float*)d_in[11];
    const float* W2    = (const float*)d_in[12];
    const float* b2    = (const float*)d_in[13];
    float* out = (float*)d_out;

    float *gb = nullptr, *lb = nullptr;
    cudaGetSymbolAddress((void**)&gb, g_bufs);
    cudaGetSymbolAddress((void**)&lb, l_bufs);
    auto G = [&](int i) { return gb + (size_t)i * BATCH * DG; };
    auto L = [&](int i) { return lb + (size_t)i * BATCH * DG; };

    cudaFuncSetAttribute(plate_hmma<true>,  cudaFuncAttributeMaxDynamicSharedMemorySize, SMEM_TOTAL);
    cudaFuncSetAttribute(plate_hmma<false>, cudaFuncAttributeMaxDynamicSharedMemorySize, SMEM_TOTAL);
    cudaFuncSetAttribute(encoder_hmma,      cudaFuncAttributeMaxDynamicSharedMemorySize, SMEM_TOTAL);
    cudaFuncSetAttribute(head_hmma,         cudaFuncAttributeMaxDynamicSharedMemorySize, SMEM_TOTAL);

    cudaMemsetAsync(L(9), 0, (size_t)BATCH * DG * sizeof(float));
    prep_kernel<<<512, 256>>>(W_ge, W_eq, W_tr, W_ab, W1, W2);

    dim3 grid(BATCH / MTILE);   // 256 CTAs, 2 CTAs/SM

    encoder_hmma<<<grid, NTHREADS, SMEM_TOTAL>>>(x, b_ge, G(0));

    // Sweep 1: descending (g[1..8] None -> g_in = g0)
    for (int n = 8; n >= 1; --n)
        plate_hmma<true><<<grid, NTHREADS, SMEM_TOTAL>>>(G(0), L(n + 1), L(n),
                                                         b_eq, b_tr, b_ab, alpha);
    // Sweep 1: ascending
    for (int n = 1; n <= 8; ++n)
        plate_hmma<false><<<grid, NTHREADS, SMEM_TOTAL>>>(G(n - 1), L(n), G(n),
                                                          b_eq, b_tr, b_ab, alpha);
    // Sweep 2: descending
    for (int n = 8; n >= 1; --n)
        plate_hmma<true><<<grid, NTHREADS, SMEM_TOTAL>>>(G(n - 1), L(n + 1), L(n),
                                                         b_eq, b_tr, b_ab, alpha);
    // Sweep 2: ascending
    for (int n = 1; n <= 8; ++n)
        plate_hmma<false><<<grid, NTHREADS, SMEM_TOTAL>>>(G(n - 1), L(n), G(n),
                                                          b_eq, b_tr, b_ab, alpha);

    head_hmma<<<grid, NTHREADS, SMEM_TOTAL>>>(G(8), L(1), b1, b2, out);
}

// round 14
// speedup vs baseline: 1.4199x; 1.2929x over previous
#include <cuda_runtime.h>
#include <cuda_fp16.h>
#include <cstdint>
#include <cstddef>

#define BATCH 16384
#define DG    256

// CTA tile: 64 rows. SMEM: A fragment planes only (hi at 0, lo at +APLANE).
// Chunk(mb 0..3, kb 0..15, lane 0..31) = 16B m16k16 A fragment (fp16).
#define APLANE    32768
#define SA_BYTES  (2 * APLANE)                     // 65,536 -> 2 CTAs/SM
#define SMEM_TOTAL SA_BYTES

#define NTHREADS  256
#define MTILE     64

// Packed 256x256 weight block, SINGLE fp16 plane: [kb16][p16][lane32][8 fp16].
#define BLK_STRIDE 65536                           // fp16 elems per packed block

// ===========================================================================
// Global scratch (__device__ globals: allocation-free rule)
// ===========================================================================
__device__ float g_bufs[9][BATCH * DG];
__device__ float l_bufs[10][BATCH * DG];
__device__ __align__(128) __half WT_eq[BLK_STRIDE];
__device__ __align__(128) __half WT_tr[BLK_STRIDE];
__device__ __align__(128) __half WT_ab[BLK_STRIDE];
__device__ __align__(128) __half WT_ge[2 * BLK_STRIDE];   // K=512: 2 K-half blocks
__device__ __align__(128) __half WT_1 [2 * BLK_STRIDE];   // K=512: 2 K-half blocks
__device__ __align__(128) __half WT_2 [4 * BLK_STRIDE];   // N=1024: 4 N-tile blocks

__device__ __forceinline__ float sigm(float x) { return 1.0f / (1.0f + expf(-x)); }

__device__ __forceinline__ uint32_t smem_to_u32(const void* p) {
    uint32_t a;
    asm("{ .reg .u64 t; cvta.to.shared.u64 t, %1; cvt.u32.u64 %0, t; }" : "=r"(a) : "l"(p));
    return a;
}

#define LDS128(r0, r1, r2, r3, addr) \
    asm volatile("ld.shared.v4.b32 {%0,%1,%2,%3}, [%4];" \
        : "=r"(r0), "=r"(r1), "=r"(r2), "=r"(r3) : "r"(addr))

#define LDG128(r0, r1, r2, r3, ptr) \
    asm volatile("ld.global.nc.v4.u32 {%0,%1,%2,%3}, [%4];" \
        : "=r"(r0), "=r"(r1), "=r"(r2), "=r"(r3) : "l"(ptr))

#define MMA16816(d, a0, a1, a2, a3, b0, b1) \
    asm volatile("mma.sync.aligned.m16n8k16.row.col.f32.f16.f16.f32 " \
        "{%0,%1,%2,%3}, {%4,%5,%6,%7}, {%8,%9}, {%0,%1,%2,%3};" \
        : "+f"((d)[0]), "+f"((d)[1]), "+f"((d)[2]), "+f"((d)[3]) \
        : "r"(a0), "r"(a1), "r"(a2), "r"(a3), "r"(b0), "r"(b1))

// fp16 split: x = hi + lo with hi = fp16(x), lo = fp16(x - hi) (~2^-22 residual)
__device__ __forceinline__ void split2(float2 x, uint32_t& h, uint32_t& l) {
    __half2 hp = __float22half2_rn(x);
    float2 hf = __half22float2(hp);
    float2 r = make_float2(x.x - hf.x, x.y - hf.y);
    __half2 lp = __float22half2_rn(r);
    h = *reinterpret_cast<uint32_t*>(&hp);
    l = *reinterpret_cast<uint32_t*>(&lp);
}

// Write one A fragment chunk (16B hi + 16B lo) from 8 fp32 values.
__device__ __forceinline__ void write_A_frag(char* sA, int mb, int kb, int lane,
                                             float e0, float e1, float e2, float e3,
                                             float o0, float o1, float o2, float o3) {
    uint32_t h0, l0, h1, l1, h2, l2, h3, l3;
    split2(make_float2(e0, e1), h0, l0);
    split2(make_float2(e2, e3), h1, l1);
    split2(make_float2(o0, o1), h2, l2);
    split2(make_float2(o2, o3), h3, l3);
    uint32_t off = (uint32_t)((mb * 16 + kb) * 32 + lane) * 16;
    *(uint4*)(sA + off) = make_uint4(h0, h1, h2, h3);
    *(uint4*)(sA + APLANE + off) = make_uint4(l0, l1, l2, l3);
}

// ===========================================================================
// prep: pack weights into fragment-order blocks (single fp16 plane).
// ===========================================================================
__device__ __forceinline__ void pack_store(__half* dst, int k, int n, float w) {
    int kb = k >> 4;
    int p = n >> 4;
    int lane = (n & 7) * 4 + ((k >> 1) & 3);
    int idx = ((n >> 3) & 1) * 4 + ((k >> 3) & 1) * 2 + (k & 1);
    size_t off = ((size_t)((kb * 16 + p) * 32 + lane)) * 8 + idx;
    dst[off] = __float2half(w);
}

__global__ void prep_kernel(const float* __restrict__ Wge, const float* __restrict__ Weq,
                            const float* __restrict__ Wtr, const float* __restrict__ Wab,
                            const float* __restrict__ W1,  const float* __restrict__ W2) {
    int i0 = blockIdx.x * 256 + threadIdx.x;
    int stride = gridDim.x * 256;
    for (int i = i0; i < 11 * 65536; i += stride) {
        int blk = i >> 16, e = i & 65535;
        int k = e >> 8, n = e & 255;
        float w;
        __half* dst;
        if (blk == 0)      { w = Weq[k * 256 + n]; dst = WT_eq; }
        else if (blk == 1) { w = Wtr[k * 256 + n]; dst = WT_tr; }
        else if (blk == 2) { w = Wab[k * 256 + n]; dst = WT_ab; }
        else if (blk <= 4) { int h = blk - 3; w = Wge[(k + h * 256) * 256 + n]; dst = WT_ge + (size_t)h * BLK_STRIDE; }
        else if (blk <= 6) { int h = blk - 5; w = W1 [(k + h * 256) * 256 + n]; dst = WT_1  + (size_t)h * BLK_STRIDE; }
        else               { int t = blk - 7; int ng = t * 256 + n;
                             w = (ng < 1000) ? W2[k * 1000 + ng] : 0.0f;
                             dst = WT_2 + (size_t)t * BLK_STRIDE; }
        pack_store(dst, k, n, w);
    }
}

// ===========================================================================
// HMMA GEMM core: acc[4][4][4] += A(fp16 hi/lo planes) @ block^T (2 products)
// 8 warps, wn = warp id (0..7); warp tile m64 x n32 (p = wn*2, wn*2+1).
// B single fp16 plane, LDG'd from gmem, register double-buffered across kc.
// D = ah*bh + al*bh  (a fully represented; b fp16 -> ~2^-11 product error).
// __syncthreads at entry (A RAW) and exit (A WAR) only.
// ===========================================================================
__device__ __forceinline__ void hmma_gemm_k256(uint32_t sA,
                                               const __half* __restrict__ blk,
                                               float acc[4][4][4],
                                               int tid, bool zero_acc) {
    if (zero_acc) {
#pragma unroll
        for (int mt = 0; mt < 4; mt++)
#pragma unroll
            for (int nt = 0; nt < 4; nt++)
#pragma unroll
                for (int i = 0; i < 4; i++) acc[mt][nt][i] = 0.f;
    }
    const int lane = tid & 31;
    const int wn = tid >> 5;
    const uint32_t abase = sA + (uint32_t)(lane * 16);
    // B base: p = wn*2 + pp; elem offset ((kc*16 + p)*32 + lane)*8
    const __half* bbase = blk + ((size_t)(wn * 2) * 32 + lane) * 8;

    uint32_t bh[2][2][4];   // [buf][pp][reg]
    // Prologue: chunk 0 -> buf 0
#pragma unroll
    for (int pp = 0; pp < 2; pp++) {
        const __half* bp = bbase + pp * 256;
        LDG128(bh[0][pp][0], bh[0][pp][1], bh[0][pp][2], bh[0][pp][3], bp);
    }

    __syncthreads();   // A fragments visible

#pragma unroll 2
    for (int kc = 0; kc < 16; kc++) {
        const int cur = kc & 1, nxt = cur ^ 1;
        if (kc < 15) {
            const __half* bk = bbase + (size_t)(kc + 1) * 4096;
#pragma unroll
            for (int pp = 0; pp < 2; pp++) {
                const __half* bp = bk + pp * 256;
                LDG128(bh[nxt][pp][0], bh[nxt][pp][1], bh[nxt][pp][2], bh[nxt][pp][3], bp);
            }
        }
#pragma unroll
        for (int mpair = 0; mpair < 2; mpair++) {
            uint32_t ah[2][4], al[2][4];
#pragma unroll
            for (int m2 = 0; m2 < 2; m2++) {
                uint32_t aaddr = abase + (uint32_t)((mpair * 2 + m2) * 8192 + kc * 512);
                LDS128(ah[m2][0], ah[m2][1], ah[m2][2], ah[m2][3], aaddr);
                LDS128(al[m2][0], al[m2][1], al[m2][2], al[m2][3], aaddr + APLANE);
            }
#pragma unroll
            for (int pp = 0; pp < 2; pp++) {
#pragma unroll
                for (int m2 = 0; m2 < 2; m2++) {
                    const int mt = mpair * 2 + m2;
                    float* aE = acc[mt][2 * pp];
                    float* aO = acc[mt][2 * pp + 1];
                    MMA16816(aE, ah[m2][0], ah[m2][1], ah[m2][2], ah[m2][3],
                             bh[cur][pp][0], bh[cur][pp][1]);
                    MMA16816(aO, ah[m2][0], ah[m2][1], ah[m2][2], ah[m2][3],
                             bh[cur][pp][2], bh[cur][pp][3]);
                    MMA16816(aE, al[m2][0], al[m2][1], al[m2][2], al[m2][3],
                             bh[cur][pp][0], bh[cur][pp][1]);
                    MMA16816(aO, al[m2][0], al[m2][1], al[m2][2], al[m2][3],
                             bh[cur][pp][2], bh[cur][pp][3]);
                }
            }
        }
    }
    __syncthreads();   // all A reads done before caller rewrites A
}

// Fill A fragment planes (64 x 256) from row-major gmem. 256 threads.
__device__ __forceinline__ void fill_A_frag(char* sA, const float* __restrict__ src,
                                            int ld, int tid) {
#pragma unroll
    for (int i = 0; i < 8; i++) {
        int idx = i * NTHREADS + tid;           // 0..2047 = (mb*16+kb)*32+lane
        int mb = idx >> 9, kb = (idx >> 5) & 15, ln = idx & 31;
        int gid = ln >> 2, qid = ln & 3;
        const float* p0 = src + (size_t)(mb * 16 + gid) * ld + kb * 16 + 2 * qid;
        float2 x0 = *(const float2*)(p0);                 // row gid,   k low
        float2 x1 = *(const float2*)(p0 + 8 * (size_t)ld);// row gid+8, k low
        float2 x2 = *(const float2*)(p0 + 8);             // row gid,   k high
        float2 x3 = *(const float2*)(p0 + 8 * (size_t)ld + 8);
        write_A_frag(sA, mb, kb, ln, x0.x, x0.y, x1.x, x1.y, x2.x, x2.y, x3.x, x3.y);
    }
}

// Per-fragment index helper (8 warps: wn 0..7, warp tile m64 x n32)
#define FRAG_SETUP() \
    const int lane = tid & 31; \
    const int wn = tid >> 5; \
    const int gid = lane >> 2, qid = lane & 3;

// acc[mt][nt]: rows mt*16+gid (+8), cols wn*32 + (nt>>1)*16 + (nt&1)*8 + qid*2

// ===========================================================================
// Fused plate kernel (HMMA): 64 rows per CTA, 256 threads, 2 CTAs/SM.
// ===========================================================================
template <bool DESC>
__global__ __launch_bounds__(NTHREADS, 2) void plate_hmma(
    const float* __restrict__ g_in, const float* __restrict__ l_in,
    float* __restrict__ out,
    const float* __restrict__ b_eq, const float* __restrict__ b_tr,
    const float* __restrict__ b_ab, const float* __restrict__ alpha_p) {
    extern __shared__ char sm[];
    char* sA_p = sm;
    uint32_t sA = smem_to_u32(sm);
    const int tid = threadIdx.x;
    const size_t rowbase = (size_t)blockIdx.x * MTILE;
    FRAG_SETUP();

    fill_A_frag(sA_p, l_in + rowbase * 256, 256, tid);

    float acc[4][4][4];
    // GEMM 1: l @ W_eq
    hmma_gemm_k256(sA, WT_eq, acc, tid, true);

    // Epilogue 1: df = g - sigmoid(acc + b_eq) -> A fragment planes
#pragma unroll
    for (int mt = 0; mt < 4; mt++) {
#pragma unroll
        for (int ntp = 0; ntp < 2; ntp++) {
            int ce = wn * 32 + ntp * 16 + qid * 2;
            int r = mt * 16 + gid;
            size_t ro = (rowbase + r) * 256;
            float2 beE = *(const float2*)(b_eq + ce);
            float2 beO = *(const float2*)(b_eq + ce + 8);
            float2 gE0 = *(const float2*)(g_in + ro + ce);
            float2 gE1 = *(const float2*)(g_in + ro + 8 * 256 + ce);
            float2 gO0 = *(const float2*)(g_in + ro + ce + 8);
            float2 gO1 = *(const float2*)(g_in + ro + 8 * 256 + ce + 8);
            const float* aE = acc[mt][2 * ntp];
            const float* aO = acc[mt][2 * ntp + 1];
            write_A_frag(sA_p, mt, wn * 2 + ntp, lane,
                         gE0.x - sigm(aE[0] + beE.x), gE0.y - sigm(aE[1] + beE.y),
                         gE1.x - sigm(aE[2] + beE.x), gE1.y - sigm(aE[3] + beE.y),
                         gO0.x - sigm(aO[0] + beO.x), gO0.y - sigm(aO[1] + beO.y),
                         gO1.x - sigm(aO[2] + beO.x), gO1.y - sigm(aO[3] + beO.y));
        }
    }

    // GEMM 2: df @ W_tr
    hmma_gemm_k256(sA, WT_tr, acc, tid, true);

    const float alpha = *alpha_p;

    if (!DESC) {
        // out = g - alpha*(acc + b_tr)
#pragma unroll
        for (int mt = 0; mt < 4; mt++) {
#pragma unroll
            for (int nt = 0; nt < 4; nt++) {
                int col = wn * 32 + (nt >> 1) * 16 + (nt & 1) * 8 + qid * 2;
                int r = mt * 16 + gid;
                size_t ro = (rowbase + r) * 256 + col;
                float2 bt = *(const float2*)(b_tr + col);
                float2 g0 = *(const float2*)(g_in + ro);
                float2 g1 = *(const float2*)(g_in + ro + 8 * 256);
                float2 o0, o1;
                o0.x = g0.x - alpha * (acc[mt][nt][0] + bt.x);
                o0.y = g0.y - alpha * (acc[mt][nt][1] + bt.y);
                o1.x = g1.x - alpha * (acc[mt][nt][2] + bt.x);
                o1.y = g1.y - alpha * (acc[mt][nt][3] + bt.y);
                *(float2*)(out + ro) = o0;
                *(float2*)(out + ro + 8 * 256) = o1;
            }
        }
    } else {
        // delta = alpha*(acc + b_tr) -> A fragment planes
#pragma unroll
        for (int mt = 0; mt < 4; mt++) {
#pragma unroll
            for (int ntp = 0; ntp < 2; ntp++) {
                int ce = wn * 32 + ntp * 16 + qid * 2;
                float2 btE = *(const float2*)(b_tr + ce);
                float2 btO = *(const float2*)(b_tr + ce + 8);
                const float* aE = acc[mt][2 * ntp];
                const float* aO = acc[mt][2 * ntp + 1];
                write_A_frag(sA_p, mt, wn * 2 + ntp, lane,
                             alpha * (aE[0] + btE.x), alpha * (aE[1] + btE.y),
                             alpha * (aE[2] + btE.x), alpha * (aE[3] + btE.y),
                             alpha * (aO[0] + btO.x), alpha * (aO[1] + btO.y),
                             alpha * (aO[2] + btO.x), alpha * (aO[3] + btO.y));
            }
        }

        // GEMM 3: delta @ W_ab
        hmma_gemm_k256(sA, WT_ab, acc, tid, true);

        // out = l + acc + b_ab
#pragma unroll
        for (int mt = 0; mt < 4; mt++) {
#pragma unroll
            for (int nt = 0; nt < 4; nt++) {
                int col = wn * 32 + (nt >> 1) * 16 + (nt & 1) * 8 + qid * 2;
                int r = mt * 16 + gid;
                size_t ro = (rowbase + r) * 256 + col;
                float2 ba = *(const float2*)(b_ab + col);
                float2 l0 = *(const float2*)(l_in + ro);
                float2 l1 = *(const float2*)(l_in + ro + 8 * 256);
                float2 o0, o1;
                o0.x = l0.x + acc[mt][nt][0] + ba.x;
                o0.y = l0.y + acc[mt][nt][1] + ba.y;
                o1.x = l1.x + acc[mt][nt][2] + ba.x;
                o1.y = l1.y + acc[mt][nt][3] + ba.y;
                *(float2*)(out + ro) = o0;
                *(float2*)(out + ro + 8 * 256) = o1;
            }
        }
    }
}

// ===========================================================================
// Encoder: g0 = relu(x @ W_ge + b_ge), K = 512 as two accumulated K=256 passes
// ===========================================================================
__global__ __launch_bounds__(NTHREADS, 2) void encoder_hmma(
    const float* __restrict__ x, const float* __restrict__ b_ge,
    float* __restrict__ g0) {
    extern __shared__ char sm[];
    char* sA_p = sm;
    uint32_t sA = smem_to_u32(sm);
    const int tid = threadIdx.x;
    const size_t rowbase = (size_t)blockIdx.x * MTILE;
    FRAG_SETUP();

    float acc[4][4][4];
    fill_A_frag(sA_p, x + rowbase * 512, 512, tid);
    hmma_gemm_k256(sA, WT_ge, acc, tid, true);
    fill_A_frag(sA_p, x + rowbase * 512 + 256, 512, tid);
    hmma_gemm_k256(sA, WT_ge + BLK_STRIDE, acc, tid, false);

#pragma unroll
    for (int mt = 0; mt < 4; mt++) {
#pragma unroll
        for (int nt = 0; nt < 4; nt++) {
            int col = wn * 32 + (nt >> 1) * 16 + (nt & 1) * 8 + qid * 2;
            int r = mt * 16 + gid;
            size_t ro = (rowbase + r) * 256 + col;
            float2 b = *(const float2*)(b_ge + col);
            float2 o0, o1;
            o0.x = fmaxf(acc[mt][nt][0] + b.x, 0.f);
            o0.y = fmaxf(acc[mt][nt][1] + b.y, 0.f);
            o1.x = fmaxf(acc[mt][nt][2] + b.x, 0.f);
            o1.y = fmaxf(acc[mt][nt][3] + b.y, 0.f);
            *(float2*)(g0 + ro) = o0;
            *(float2*)(g0 + ro + 8 * 256) = o1;
        }
    }
}

// ===========================================================================
// Head: h = relu([g8||l1] @ W1 + b1); out = h @ W2 + b2  (N=1000, 4 tiles)
// ===========================================================================
__global__ __launch_bounds__(NTHREADS, 2) void head_hmma(
    const float* __restrict__ g8, const float* __restrict__ l1,
    const float* __restrict__ b1, const float* __restrict__ b2,
    float* __restrict__ out) {
    extern __shared__ char sm[];
    char* sA_p = sm;
    uint32_t sA = smem_to_u32(sm);
    const int tid = threadIdx.x;
    const size_t rowbase = (size_t)blockIdx.x * MTILE;
    FRAG_SETUP();

    float acc[4][4][4];
    fill_A_frag(sA_p, g8 + rowbase * 256, 256, tid);
    hmma_gemm_k256(sA, WT_1, acc, tid, true);
    fill_A_frag(sA_p, l1 + rowbase * 256, 256, tid);
    hmma_gemm_k256(sA, WT_1 + BLK_STRIDE, acc, tid, false);

    // h = relu(acc + b1) -> A fragment planes
#pragma unroll
    for (int mt = 0; mt < 4; mt++) {
#pragma unroll
        for (int ntp = 0; ntp < 2; ntp++) {
            int ce = wn * 32 + ntp * 16 + qid * 2;
            float2 bE = *(const float2*)(b1 + ce);
            float2 bO = *(const float2*)(b1 + ce + 8);
            const float* aE = acc[mt][2 * ntp];
            const float* aO = acc[mt][2 * ntp + 1];
            write_A_frag(sA_p, mt, wn * 2 + ntp, lane,
                         fmaxf(aE[0] + bE.x, 0.f), fmaxf(aE[1] + bE.y, 0.f),
                         fmaxf(aE[2] + bE.x, 0.f), fmaxf(aE[3] + bE.y, 0.f),
                         fmaxf(aO[0] + bO.x, 0.f), fmaxf(aO[1] + bO.y, 0.f),
                         fmaxf(aO[2] + bO.x, 0.f), fmaxf(aO[3] + bO.y, 0.f));
        }
    }

    for (int t = 0; t < 4; t++) {
        hmma_gemm_k256(sA, WT_2 + (size_t)t * BLK_STRIDE, acc, tid, true);
#pragma unroll
        for (int mt = 0; mt < 4; mt++) {
#pragma unroll
            for (int nt = 0; nt < 4; nt++) {
                int col = t * 256 + wn * 32 + (nt >> 1) * 16 + (nt & 1) * 8 + qid * 2;
                if (col < 1000) {
                    int r = mt * 16 + gid;
                    size_t ro = (rowbase + r) * 1000 + col;
                    float2 b = *(const float2*)(b2 + col);
                    float2 o0, o1;
                    o0.x = acc[mt][nt][0] + b.x;
                    o0.y = acc[mt][nt][1] + b.y;
                    o1.x = acc[mt][nt][2] + b.x;
                    o1.y = acc[mt][nt][3] + b.y;
                    *(float2*)(out + ro) = o0;
                    *(float2*)(out + ro + 8 * 1000) = o1;
                }
            }
        }
    }
}

// ===========================================================================
extern "C" void kernel_launch(void* const* d_in, const int* in_sizes, int n_in,
                              void* d_out, int out_size) {
    (void)in_sizes; (void)n_in; (void)out_size;
    const float* x     = (const float*)d_in[0];
    const float* W_ge  = (const float*)d_in[1];
    const float* b_ge  = (const float*)d_in[2];
    const float* W_eq  = (const float*)d_in[3];
    const float* b_eq  = (const float*)d_in[4];
    const float* W_tr  = (const float*)d_in[5];
    const float* b_tr  = (const float*)d_in[6];
    const float* W_ab  = (const float*)d_in[7];
    const float* b_ab  = (const float*)d_in[8];
    const float* alpha = (const float*)d_in[9];
    const float* W1    = (const float*)d_in[10];
    const float* b1    = (const float*)d_in[11];
    const float* W2    = (const float*)d_in[12];
    const float* b2    = (const float*)d_in[13];
    float* out = (float*)d_out;

    float *gb = nullptr, *lb = nullptr;
    cudaGetSymbolAddress((void**)&gb, g_bufs);
    cudaGetSymbolAddress((void**)&lb, l_bufs);
    auto G = [&](int i) { return gb + (size_t)i * BATCH * DG; };
    auto L = [&](int i) { return lb + (size_t)i * BATCH * DG; };

    cudaFuncSetAttribute(plate_hmma<true>,  cudaFuncAttributeMaxDynamicSharedMemorySize, SMEM_TOTAL);
    cudaFuncSetAttribute(plate_hmma<false>, cudaFuncAttributeMaxDynamicSharedMemorySize, SMEM_TOTAL);
    cudaFuncSetAttribute(encoder_hmma,      cudaFuncAttributeMaxDynamicSharedMemorySize, SMEM_TOTAL);
    cudaFuncSetAttribute(head_hmma,         cudaFuncAttributeMaxDynamicSharedMemorySize, SMEM_TOTAL);

    cudaMemsetAsync(L(9), 0, (size_t)BATCH * DG * sizeof(float));
    prep_kernel<<<512, 256>>>(W_ge, W_eq, W_tr, W_ab, W1, W2);

    dim3 grid(BATCH / MTILE);   // 256 CTAs, 2 CTAs/SM

    encoder_hmma<<<grid, NTHREADS, SMEM_TOTAL>>>(x, b_ge, G(0));

    // Sweep 1: descending (g[1..8] None -> g_in = g0)
    for (int n = 8; n >= 1; --n)
        plate_hmma<true><<<grid, NTHREADS, SMEM_TOTAL>>>(G(0), L(n + 1), L(n),
                                                         b_eq, b_tr, b_ab, alpha);
    // Sweep 1: ascending
    for (int n = 1; n <= 8; ++n)
        plate_hmma<false><<<grid, NTHREADS, SMEM_TOTAL>>>(G(n - 1), L(n), G(n),
                                                          b_eq, b_tr, b_ab, alpha);
    // Sweep 2: descending
    for (int n = 8; n >= 1; --n)
        plate_hmma<true><<<grid, NTHREADS, SMEM_TOTAL>>>(G(n - 1), L(n + 1), L(n),
                                                         b_eq, b_tr, b_ab, alpha);
    // Sweep 2: ascending
    for (int n = 1; n <= 8; ++n)
        plate_hmma<false><<<grid, NTHREADS, SMEM_TOTAL>>>(G(n - 1), L(n), G(n),
                                                          b_eq, b_tr, b_ab, alpha);

    head_hmma<<<grid, NTHREADS, SMEM_TOTAL>>>(G(8), L(1), b1, b2, out);
}

// round 16
// speedup vs baseline: 1.5299x; 1.0775x over previous
#include <cuda_runtime.h>
#include <cuda_fp16.h>
#include <cstdint>
#include <cstddef>

#define BATCH 16384
#define DG    256

#define APLANE    32768
#define SA_BYTES  (2 * APLANE)                     // 65,536 -> 2 CTAs/SM
#define SMEM_TOTAL SA_BYTES

#define NTHREADS  256
#define MTILE     64
#define NTILES    (BATCH / MTILE)                  // 256

// Packed activation tile: [plane hi|lo][2048 chunks][8 halfs]; 32768 halfs/tile.
#define TILE_HALFS 32768

// Packed 256x256 weight block, SINGLE fp16 plane: [kb16][p16][lane32][8 fp16].
#define BLK_STRIDE 65536

// ===========================================================================
// Global scratch (__device__ globals: allocation-free rule)
// ===========================================================================
__device__ __half g_bufs[9][(size_t)NTILES * TILE_HALFS];
__device__ __half l_bufs[10][(size_t)NTILES * TILE_HALFS];
__device__ __align__(128) __half WT_eq[BLK_STRIDE];
__device__ __align__(128) __half WT_tr[BLK_STRIDE];
__device__ __align__(128) __half WT_ab[BLK_STRIDE];
__device__ __align__(128) __half WT_ge[2 * BLK_STRIDE];
__device__ __align__(128) __half WT_1 [2 * BLK_STRIDE];
__device__ __align__(128) __half WT_2 [4 * BLK_STRIDE];

__device__ __forceinline__ float sigm(float x) { return 1.0f / (1.0f + expf(-x)); }

__device__ __forceinline__ uint32_t smem_to_u32(const void* p) {
    uint32_t a;
    asm("{ .reg .u64 t; cvta.to.shared.u64 t, %1; cvt.u32.u64 %0, t; }" : "=r"(a) : "l"(p));
    return a;
}

#define LDS128(r0, r1, r2, r3, addr) \
    asm volatile("ld.shared.v4.b32 {%0,%1,%2,%3}, [%4];" \
        : "=r"(r0), "=r"(r1), "=r"(r2), "=r"(r3) : "r"(addr))

#define LDG128(r0, r1, r2, r3, ptr) \
    asm volatile("ld.global.nc.v4.u32 {%0,%1,%2,%3}, [%4];" \
        : "=r"(r0), "=r"(r1), "=r"(r2), "=r"(r3) : "l"(ptr))

#define MMA16816(d, a0, a1, a2, a3, b0, b1) \
    asm volatile("mma.sync.aligned.m16n8k16.row.col.f32.f16.f16.f32 " \
        "{%0,%1,%2,%3}, {%4,%5,%6,%7}, {%8,%9}, {%0,%1,%2,%3};" \
        : "+f"((d)[0]), "+f"((d)[1]), "+f"((d)[2]), "+f"((d)[3]) \
        : "r"(a0), "r"(a1), "r"(a2), "r"(a3), "r"(b0), "r"(b1))

__device__ __forceinline__ void split2(float2 x, uint32_t& h, uint32_t& l) {
    __half2 hp = __float22half2_rn(x);
    float2 hf = __half22float2(hp);
    float2 r = make_float2(x.x - hf.x, x.y - hf.y);
    __half2 lp = __float22half2_rn(r);
    h = *reinterpret_cast<uint32_t*>(&hp);
    l = *reinterpret_cast<uint32_t*>(&lp);
}

// Pack 8 fp32 (e0..e3,o0..o3) into hi/lo uint4 chunks.
__device__ __forceinline__ void pack8(const float* v, uint4& hi, uint4& lo) {
    split2(make_float2(v[0], v[1]), hi.x, lo.x);
    split2(make_float2(v[2], v[3]), hi.y, lo.y);
    split2(make_float2(v[4], v[5]), hi.z, lo.z);
    split2(make_float2(v[6], v[7]), hi.w, lo.w);
}
__device__ __forceinline__ void unpack8(uint4 hi, uint4 lo, float* v) {
    const uint32_t* hp = (const uint32_t*)&hi;
    const uint32_t* lp = (const uint32_t*)&lo;
#pragma unroll
    for (int j = 0; j < 4; j++) {
        float2 a = __half22float2(*(const __half2*)&hp[j]);
        float2 b = __half22float2(*(const __half2*)&lp[j]);
        v[2 * j] = a.x + b.x;
        v[2 * j + 1] = a.y + b.y;
    }
}

#define FRAG_OFF(mb, kb, lane) ((size_t)(((mb) * 16 + (kb)) * 32 + (lane)) * 8)

// Load/store a packed activation fragment (gmem tile, halfs).
__device__ __forceinline__ void load_pack8(const __half* tile, int mb, int kb, int lane,
                                           float* v) {
    size_t off = FRAG_OFF(mb, kb, lane);
    uint4 hi = *(const uint4*)(tile + off);
    uint4 lo = *(const uint4*)(tile + 16384 + off);
    unpack8(hi, lo, v);
}
__device__ __forceinline__ void store_pack8(__half* tile, int mb, int kb, int lane,
                                            const float* v) {
    uint4 hi, lo;
    pack8(v, hi, lo);
    size_t off = FRAG_OFF(mb, kb, lane);
    *(uint4*)(tile + off) = hi;
    *(uint4*)(tile + 16384 + off) = lo;
}

// Write one A fragment chunk to SMEM planes from 8 fp32 values.
__device__ __forceinline__ void write_A_frag(char* sA, int mb, int kb, int lane,
                                             const float* v) {
    uint4 hi, lo;
    pack8(v, hi, lo);
    uint32_t off = (uint32_t)((mb * 16 + kb) * 32 + lane) * 16;
    *(uint4*)(sA + off) = hi;
    *(uint4*)(sA + APLANE + off) = lo;
}

// ===========================================================================
// prep: pack weights into fragment-order blocks (single fp16 plane).
// ===========================================================================
__device__ __forceinline__ void pack_store(__half* dst, int k, int n, float w) {
    int kb = k >> 4;
    int p = n >> 4;
    int lane = (n & 7) * 4 + ((k >> 1) & 3);
    int idx = ((n >> 3) & 1) * 4 + ((k >> 3) & 1) * 2 + (k & 1);
    size_t off = ((size_t)((kb * 16 + p) * 32 + lane)) * 8 + idx;
    dst[off] = __float2half(w);
}

__global__ void prep_kernel(const float* __restrict__ Wge, const float* __restrict__ Weq,
                            const float* __restrict__ Wtr, const float* __restrict__ Wab,
                            const float* __restrict__ W1,  const float* __restrict__ W2) {
    int i0 = blockIdx.x * 256 + threadIdx.x;
    int stride = gridDim.x * 256;
    for (int i = i0; i < 11 * 65536; i += stride) {
        int blk = i >> 16, e = i & 65535;
        int k = e >> 8, n = e & 255;
        float w;
        __half* dst;
        if (blk == 0)      { w = Weq[k * 256 + n]; dst = WT_eq; }
        else if (blk == 1) { w = Wtr[k * 256 + n]; dst = WT_tr; }
        else if (blk == 2) { w = Wab[k * 256 + n]; dst = WT_ab; }
        else if (blk <= 4) { int h = blk - 3; w = Wge[(k + h * 256) * 256 + n]; dst = WT_ge + (size_t)h * BLK_STRIDE; }
        else if (blk <= 6) { int h = blk - 5; w = W1 [(k + h * 256) * 256 + n]; dst = WT_1  + (size_t)h * BLK_STRIDE; }
        else               { int t = blk - 7; int ng = t * 256 + n;
                             w = (ng < 1000) ? W2[k * 1000 + ng] : 0.0f;
                             dst = WT_2 + (size_t)t * BLK_STRIDE; }
        pack_store(dst, k, n, w);
    }
}

// ===========================================================================
// HMMA GEMM core (fp16 2-product; MMA order gives same-acc distance 4).
// ===========================================================================
__device__ __forceinline__ void hmma_gemm_k256(uint32_t sA,
                                               const __half* __restrict__ blk,
                                               float acc[4][4][4],
                                               int tid, bool zero_acc) {
    if (zero_acc) {
#pragma unroll
        for (int mt = 0; mt < 4; mt++)
#pragma unroll
            for (int nt = 0; nt < 4; nt++)
#pragma unroll
                for (int i = 0; i < 4; i++) acc[mt][nt][i] = 0.f;
    }
    const int lane = tid & 31;
    const int wn = tid >> 5;
    const uint32_t abase = sA + (uint32_t)(lane * 16);
    const __half* bbase = blk + ((size_t)(wn * 2) * 32 + lane) * 8;

    uint32_t bh[2][2][4];
#pragma unroll
    for (int pp = 0; pp < 2; pp++) {
        const __half* bp = bbase + pp * 256;
        LDG128(bh[0][pp][0], bh[0][pp][1], bh[0][pp][2], bh[0][pp][3], bp);
    }

    __syncthreads();   // A fragments visible

#pragma unroll 2
    for (int kc = 0; kc < 16; kc++) {
        const int cur = kc & 1, nxt = cur ^ 1;
        if (kc < 15) {
            const __half* bk = bbase + (size_t)(kc + 1) * 4096;
#pragma unroll
            for (int pp = 0; pp < 2; pp++) {
                const __half* bp = bk + pp * 256;
                LDG128(bh[nxt][pp][0], bh[nxt][pp][1], bh[nxt][pp][2], bh[nxt][pp][3], bp);
            }
        }
#pragma unroll
        for (int mpair = 0; mpair < 2; mpair++) {
            uint32_t ah[2][4], al[2][4];
#pragma unroll
            for (int m2 = 0; m2 < 2; m2++) {
                uint32_t aaddr = abase + (uint32_t)((mpair * 2 + m2) * 8192 + kc * 512);
                LDS128(ah[m2][0], ah[m2][1], ah[m2][2], ah[m2][3], aaddr);
                LDS128(al[m2][0], al[m2][1], al[m2][2], al[m2][3], aaddr + APLANE);
            }
#pragma unroll
            for (int pp = 0; pp < 2; pp++) {
                float* aE0 = acc[mpair * 2 + 0][2 * pp];
                float* aO0 = acc[mpair * 2 + 0][2 * pp + 1];
                float* aE1 = acc[mpair * 2 + 1][2 * pp];
                float* aO1 = acc[mpair * 2 + 1][2 * pp + 1];
                MMA16816(aE0, ah[0][0], ah[0][1], ah[0][2], ah[0][3],
                         bh[cur][pp][0], bh[cur][pp][1]);
                MMA16816(aO0, ah[0][0], ah[0][1], ah[0][2], ah[0][3],
                         bh[cur][pp][2], bh[cur][pp][3]);
                MMA16816(aE1, ah[1][0], ah[1][1], ah[1][2], ah[1][3],
                         bh[cur][pp][0], bh[cur][pp][1]);
                MMA16816(aO1, ah[1][0], ah[1][1], ah[1][2], ah[1][3],
                         bh[cur][pp][2], bh[cur][pp][3]);
                MMA16816(aE0, al[0][0], al[0][1], al[0][2], al[0][3],
                         bh[cur][pp][0], bh[cur][pp][1]);
                MMA16816(aO0, al[0][0], al[0][1], al[0][2], al[0][3],
                         bh[cur][pp][2], bh[cur][pp][3]);
                MMA16816(aE1, al[1][0], al[1][1], al[1][2], al[1][3],
                         bh[cur][pp][0], bh[cur][pp][1]);
                MMA16816(aO1, al[1][0], al[1][1], al[1][2], al[1][3],
                         bh[cur][pp][2], bh[cur][pp][3]);
            }
        }
    }
    __syncthreads();   // all A reads done before caller rewrites A
}

// Fill A planes from a PACKED gmem tile. Gmem tile layout == SMEM layout
// (hi plane 2048 chunks then lo plane 2048 chunks, contiguous), so this is
// a straight 64KB copy: 4096 chunks of 16B. FIX from round 15: copy ALL
// 4096 chunks (was 2048 -> lo plane stale).
__device__ __forceinline__ void fill_A_packed(char* sA, const __half* __restrict__ tile,
                                              int tid) {
#pragma unroll
    for (int i = 0; i < 16; i++) {
        int idx = i * NTHREADS + tid;            // 0..4095
        uint4 v = *(const uint4*)(tile + (size_t)idx * 8);
        *(uint4*)(sA + (size_t)idx * 16) = v;
    }
}

// Fill A planes from fp32 row-major gmem (encoder input x only).
__device__ __forceinline__ void fill_A_f32(char* sA, const float* __restrict__ src,
                                           int ld, int tid) {
#pragma unroll
    for (int i = 0; i < 8; i++) {
        int idx = i * NTHREADS + tid;
        int mb = idx >> 9, kb = (idx >> 5) & 15, ln = idx & 31;
        int gid = ln >> 2, qid = ln & 3;
        const float* p0 = src + (size_t)(mb * 16 + gid) * ld + kb * 16 + 2 * qid;
        float v[8];
        float2 x0 = *(const float2*)(p0);
        float2 x1 = *(const float2*)(p0 + 8 * (size_t)ld);
        float2 x2 = *(const float2*)(p0 + 8);
        float2 x3 = *(const float2*)(p0 + 8 * (size_t)ld + 8);
        v[0] = x0.x; v[1] = x0.y; v[2] = x1.x; v[3] = x1.y;
        v[4] = x2.x; v[5] = x2.y; v[6] = x3.x; v[7] = x3.y;
        write_A_frag(sA, mb, kb, ln, v);
    }
}

#define FRAG_SETUP() \
    const int lane = tid & 31; \
    const int wn = tid >> 5; \
    const int gid = lane >> 2, qid = lane & 3;

// ===========================================================================
// Fused plate kernel: packed activation tiles. 64 rows/CTA, 2 CTAs/SM.
// ===========================================================================
template <bool DESC>
__global__ __launch_bounds__(NTHREADS, 2) void plate_hmma(
    const __half* __restrict__ g_in, const __half* __restrict__ l_in,
    __half* __restrict__ out,
    const float* __restrict__ b_eq, const float* __restrict__ b_tr,
    const float* __restrict__ b_ab, const float* __restrict__ alpha_p) {
    extern __shared__ char sm[];
    char* sA_p = sm;
    uint32_t sA = smem_to_u32(sm);
    const int tid = threadIdx.x;
    const size_t tb = blockIdx.x;
    const __half* gt = g_in + tb * TILE_HALFS;
    const __half* lt = l_in + tb * TILE_HALFS;
    __half* ot = out + tb * TILE_HALFS;
    FRAG_SETUP();

    fill_A_packed(sA_p, lt, tid);

    float acc[4][4][4];
    hmma_gemm_k256(sA, WT_eq, acc, tid, true);

    // Epilogue 1: df = g - sigmoid(acc + b_eq) -> A planes
#pragma unroll
    for (int mt = 0; mt < 4; mt++) {
#pragma unroll
        for (int ntp = 0; ntp < 2; ntp++) {
            int kbf = wn * 2 + ntp;
            int ce = wn * 32 + ntp * 16 + qid * 2;
            float2 beE = *(const float2*)(b_eq + ce);
            float2 beO = *(const float2*)(b_eq + ce + 8);
            float gv[8], v[8];
            load_pack8(gt, mt, kbf, lane, gv);
            const float* aE = acc[mt][2 * ntp];
            const float* aO = acc[mt][2 * ntp + 1];
            v[0] = gv[0] - sigm(aE[0] + beE.x);
            v[1] = gv[1] - sigm(aE[1] + beE.y);
            v[2] = gv[2] - sigm(aE[2] + beE.x);
            v[3] = gv[3] - sigm(aE[3] + beE.y);
            v[4] = gv[4] - sigm(aO[0] + beO.x);
            v[5] = gv[5] - sigm(aO[1] + beO.y);
            v[6] = gv[6] - sigm(aO[2] + beO.x);
            v[7] = gv[7] - sigm(aO[3] + beO.y);
            write_A_frag(sA_p, mt, kbf, lane, v);
        }
    }

    hmma_gemm_k256(sA, WT_tr, acc, tid, true);

    const float alpha = *alpha_p;

    if (!DESC) {
        // out = g - alpha*(acc + b_tr), packed
#pragma unroll
        for (int mt = 0; mt < 4; mt++) {
#pragma unroll
            for (int ntp = 0; ntp < 2; ntp++) {
                int kbf = wn * 2 + ntp;
                int ce = wn * 32 + ntp * 16 + qid * 2;
                float2 btE = *(const float2*)(b_tr + ce);
                float2 btO = *(const float2*)(b_tr + ce + 8);
                float gv[8], v[8];
                load_pack8(gt, mt, kbf, lane, gv);
                const float* aE = acc[mt][2 * ntp];
                const float* aO = acc[mt][2 * ntp + 1];
                v[0] = gv[0] - alpha * (aE[0] + btE.x);
                v[1] = gv[1] - alpha * (aE[1] + btE.y);
                v[2] = gv[2] - alpha * (aE[2] + btE.x);
                v[3] = gv[3] - alpha * (aE[3] + btE.y);
                v[4] = gv[4] - alpha * (aO[0] + btO.x);
                v[5] = gv[5] - alpha * (aO[1] + btO.y);
                v[6] = gv[6] - alpha * (aO[2] + btO.x);
                v[7] = gv[7] - alpha * (aO[3] + btO.y);
                store_pack8(ot, mt, kbf, lane, v);
            }
        }
    } else {
        // delta = alpha*(acc + b_tr) -> A planes
#pragma unroll
        for (int mt = 0; mt < 4; mt++) {
#pragma unroll
            for (int ntp = 0; ntp < 2; ntp++) {
                int kbf = wn * 2 + ntp;
                int ce = wn * 32 + ntp * 16 + qid * 2;
                float2 btE = *(const float2*)(b_tr + ce);
                float2 btO = *(const float2*)(b_tr + ce + 8);
                float v[8];
                const float* aE = acc[mt][2 * ntp];
                const float* aO = acc[mt][2 * ntp + 1];
                v[0] = alpha * (aE[0] + btE.x);
                v[1] = alpha * (aE[1] + btE.y);
                v[2] = alpha * (aE[2] + btE.x);
                v[3] = alpha * (aE[3] + btE.y);
                v[4] = alpha * (aO[0] + btO.x);
                v[5] = alpha * (aO[1] + btO.y);
                v[6] = alpha * (aO[2] + btO.x);
                v[7] = alpha * (aO[3] + btO.y);
                write_A_frag(sA_p, mt, kbf, lane, v);
            }
        }

        hmma_gemm_k256(sA, WT_ab, acc, tid, true);

        // out = l + acc + b_ab, packed
#pragma unroll
        for (int mt = 0; mt < 4; mt++) {
#pragma unroll
            for (int ntp = 0; ntp < 2; ntp++) {
                int kbf = wn * 2 + ntp;
                int ce = wn * 32 + ntp * 16 + qid * 2;
                float2 baE = *(const float2*)(b_ab + ce);
                float2 baO = *(const float2*)(b_ab + ce + 8);
                float lv[8], v[8];
                load_pack8(lt, mt, kbf, lane, lv);
                const float* aE = acc[mt][2 * ntp];
                const float* aO = acc[mt][2 * ntp + 1];
                v[0] = lv[0] + aE[0] + baE.x;
                v[1] = lv[1] + aE[1] + baE.y;
                v[2] = lv[2] + aE[2] + baE.x;
                v[3] = lv[3] + aE[3] + baE.y;
                v[4] = lv[4] + aO[0] + baO.x;
                v[5] = lv[5] + aO[1] + baO.y;
                v[6] = lv[6] + aO[2] + baO.x;
                v[7] = lv[7] + aO[3] + baO.y;
                store_pack8(ot, mt, kbf, lane, v);
            }
        }
    }
}

// ===========================================================================
// Encoder: g0 = relu(x @ W_ge + b_ge) -> packed tile
// ===========================================================================
__global__ __launch_bounds__(NTHREADS, 2) void encoder_hmma(
    const float* __restrict__ x, const float* __restrict__ b_ge,
    __half* __restrict__ g0) {
    extern __shared__ char sm[];
    char* sA_p = sm;
    uint32_t sA = smem_to_u32(sm);
    const int tid = threadIdx.x;
    const size_t tb = blockIdx.x;
    const size_t rowbase = tb * MTILE;
    __half* g0t = g0 + tb * TILE_HALFS;
    FRAG_SETUP();

    float acc[4][4][4];
    fill_A_f32(sA_p, x + rowbase * 512, 512, tid);
    hmma_gemm_k256(sA, WT_ge, acc, tid, true);
    fill_A_f32(sA_p, x + rowbase * 512 + 256, 512, tid);
    hmma_gemm_k256(sA, WT_ge + BLK_STRIDE, acc, tid, false);

#pragma unroll
    for (int mt = 0; mt < 4; mt++) {
#pragma unroll
        for (int ntp = 0; ntp < 2; ntp++) {
            int kbf = wn * 2 + ntp;
            int ce = wn * 32 + ntp * 16 + qid * 2;
            float2 bE = *(const float2*)(b_ge + ce);
            float2 bO = *(const float2*)(b_ge + ce + 8);
            float v[8];
            const float* aE = acc[mt][2 * ntp];
            const float* aO = acc[mt][2 * ntp + 1];
            v[0] = fmaxf(aE[0] + bE.x, 0.f);
            v[1] = fmaxf(aE[1] + bE.y, 0.f);
            v[2] = fmaxf(aE[2] + bE.x, 0.f);
            v[3] = fmaxf(aE[3] + bE.y, 0.f);
            v[4] = fmaxf(aO[0] + bO.x, 0.f);
            v[5] = fmaxf(aO[1] + bO.y, 0.f);
            v[6] = fmaxf(aO[2] + bO.x, 0.f);
            v[7] = fmaxf(aO[3] + bO.y, 0.f);
            store_pack8(g0t, mt, kbf, lane, v);
        }
    }
}

// ===========================================================================
// Head: h = relu([g8||l1] @ W1 + b1); out = h @ W2 + b2  (fp32 output)
// ===========================================================================
__global__ __launch_bounds__(NTHREADS, 2) void head_hmma(
    const __half* __restrict__ g8, const __half* __restrict__ l1,
    const float* __restrict__ b1, const float* __restrict__ b2,
    float* __restrict__ out) {
    extern __shared__ char sm[];
    char* sA_p = sm;
    uint32_t sA = smem_to_u32(sm);
    const int tid = threadIdx.x;
    const size_t tb = blockIdx.x;
    const size_t rowbase = tb * MTILE;
    FRAG_SETUP();

    float acc[4][4][4];
    fill_A_packed(sA_p, g8 + tb * TILE_HALFS, tid);
    hmma_gemm_k256(sA, WT_1, acc, tid, true);
    fill_A_packed(sA_p, l1 + tb * TILE_HALFS, tid);
    hmma_gemm_k256(sA, WT_1 + BLK_STRIDE, acc, tid, false);

    // h = relu(acc + b1) -> A planes
#pragma unroll
    for (int mt = 0; mt < 4; mt++) {
#pragma unroll
        for (int ntp = 0; ntp < 2; ntp++) {
            int kbf = wn * 2 + ntp;
            int ce = wn * 32 + ntp * 16 + qid * 2;
            float2 bE = *(const float2*)(b1 + ce);
            float2 bO = *(const float2*)(b1 + ce + 8);
            float v[8];
            const float* aE = acc[mt][2 * ntp];
            const float* aO = acc[mt][2 * ntp + 1];
            v[0] = fmaxf(aE[0] + bE.x, 0.f);
            v[1] = fmaxf(aE[1] + bE.y, 0.f);
            v[2] = fmaxf(aE[2] + bE.x, 0.f);
            v[3] = fmaxf(aE[3] + bE.y, 0.f);
            v[4] = fmaxf(aO[0] + bO.x, 0.f);
            v[5] = fmaxf(aO[1] + bO.y, 0.f);
            v[6] = fmaxf(aO[2] + bO.x, 0.f);
            v[7] = fmaxf(aO[3] + bO.y, 0.f);
            write_A_frag(sA_p, mt, kbf, lane, v);
        }
    }

    for (int t = 0; t < 4; t++) {
        hmma_gemm_k256(sA, WT_2 + (size_t)t * BLK_STRIDE, acc, tid, true);
#pragma unroll
        for (int mt = 0; mt < 4; mt++) {
#pragma unroll
            for (int nt = 0; nt < 4; nt++) {
                int col = t * 256 + wn * 32 + (nt >> 1) * 16 + (nt & 1) * 8 + qid * 2;
                if (col < 1000) {
                    int r = mt * 16 + gid;
                    size_t ro = (rowbase + r) * 1000 + col;
                    float2 b = *(const float2*)(b2 + col);
                    float2 o0, o1;
                    o0.x = acc[mt][nt][0] + b.x;
                    o0.y = acc[mt][nt][1] + b.y;
                    o1.x = acc[mt][nt][2] + b.x;
                    o1.y = acc[mt][nt][3] + b.y;
                    *(float2*)(out + ro) = o0;
                    *(float2*)(out + ro + 8 * 1000) = o1;
                }
            }
        }
    }
}

// ===========================================================================
extern "C" void kernel_launch(void* const* d_in, const int* in_sizes, int n_in,
                              void* d_out, int out_size) {
    (void)in_sizes; (void)n_in; (void)out_size;
    const float* x     = (const float*)d_in[0];
    const float* W_ge  = (const float*)d_in[1];
    const float* b_ge  = (const float*)d_in[2];
    const float* W_eq  = (const float*)d_in[3];
    const float* b_eq  = (const float*)d_in[4];
    const float* W_tr  = (const float*)d_in[5];
    const float* b_tr  = (const float*)d_in[6];
    const float* W_ab  = (const float*)d_in[7];
    const float* b_ab  = (const float*)d_in[8];
    const float* alpha = (const float*)d_in[9];
    const float* W1    = (const float*)d_in[10];
    const float* b1    = (const float*)d_in[11];
    const float* W2    = (const float*)d_in[12];
    const float* b2    = (const float*)d_in[13];
    float* out = (float*)d_out;

    __half *gb = nullptr, *lb = nullptr;
    cudaGetSymbolAddress((void**)&gb, g_bufs);
    cudaGetSymbolAddress((void**)&lb, l_bufs);
    auto G = [&](int i) { return gb + (size_t)i * NTILES * TILE_HALFS; };
    auto L = [&](int i) { return lb + (size_t)i * NTILES * TILE_HALFS; };

    cudaFuncSetAttribute(plate_hmma<true>,  cudaFuncAttributeMaxDynamicSharedMemorySize, SMEM_TOTAL);
    cudaFuncSetAttribute(plate_hmma<false>, cudaFuncAttributeMaxDynamicSharedMemorySize, SMEM_TOTAL);
    cudaFuncSetAttribute(encoder_hmma,      cudaFuncAttributeMaxDynamicSharedMemorySize, SMEM_TOTAL);
    cudaFuncSetAttribute(head_hmma,         cudaFuncAttributeMaxDynamicSharedMemorySize, SMEM_TOTAL);

    cudaMemsetAsync(L(9), 0, (size_t)NTILES * TILE_HALFS * sizeof(__half));
    prep_kernel<<<512, 256>>>(W_ge, W_eq, W_tr, W_ab, W1, W2);

    dim3 grid(NTILES);   // 256 CTAs, 2 CTAs/SM

    encoder_hmma<<<grid, NTHREADS, SMEM_TOTAL>>>(x, b_ge, G(0));

    // Sweep 1: descending (g[1..8] None -> g_in = g0)
    for (int n = 8; n >= 1; --n)
        plate_hmma<true><<<grid, NTHREADS, SMEM_TOTAL>>>(G(0), L(n + 1), L(n),
                                                         b_eq, b_tr, b_ab, alpha);
    // Sweep 1: ascending
    for (int n = 1; n <= 8; ++n)
        plate_hmma<false><<<grid, NTHREADS, SMEM_TOTAL>>>(G(n - 1), L(n), G(n),
                                                          b_eq, b_tr, b_ab, alpha);
    // Sweep 2: descending
    for (int n = 8; n >= 1; --n)
        plate_hmma<true><<<grid, NTHREADS, SMEM_TOTAL>>>(G(n - 1), L(n + 1), L(n),
                                                         b_eq, b_tr, b_ab, alpha);
    // Sweep 2: ascending
    for (int n = 1; n <= 8; ++n)
        plate_hmma<false><<<grid, NTHREADS, SMEM_TOTAL>>>(G(n - 1), L(n), G(n),
                                                          b_eq, b_tr, b_ab, alpha);

    head_hmma<<<grid, NTHREADS, SMEM_TOTAL>>>(G(8), L(1), b1, b2, out);
}

// round 17
// speedup vs baseline: 2.2046x; 1.4410x over previous
#include <cuda_runtime.h>
#include <cuda_fp16.h>
#include <cstdint>
#include <cstddef>

#define BATCH 16384
#define DG    256

// SMEM: single fp16 A plane (hi only). 32KB -> 2 CTAs/SM with room to spare.
#define SA_BYTES  32768
#define SMEM_TOTAL SA_BYTES

#define NTHREADS  256
#define MTILE     64
#define NTILES    (BATCH / MTILE)                  // 256

// Packed activation tile in gmem: hi plane (2048 chunks) + lo plane; the
// hi/lo pair keeps chained activations accurate to 2^-22 across plates.
// Only the hi plane feeds the MMA (A operand quantized to fp16 per GEMM).
#define TILE_HALFS 32768

// Packed 256x256 weight block, SINGLE fp16 plane: [kb16][p16][lane32][8 fp16].
#define BLK_STRIDE 65536

// ===========================================================================
// Global scratch (__device__ globals: allocation-free rule)
// ===========================================================================
__device__ __half g_bufs[9][(size_t)NTILES * TILE_HALFS];
__device__ __half l_bufs[10][(size_t)NTILES * TILE_HALFS];
__device__ __align__(128) __half WT_eq[BLK_STRIDE];
__device__ __align__(128) __half WT_tr[BLK_STRIDE];
__device__ __align__(128) __half WT_ab[BLK_STRIDE];
__device__ __align__(128) __half WT_ge[2 * BLK_STRIDE];
__device__ __align__(128) __half WT_1 [2 * BLK_STRIDE];
__device__ __align__(128) __half WT_2 [4 * BLK_STRIDE];

__device__ __forceinline__ float sigm(float x) { return 1.0f / (1.0f + expf(-x)); }

__device__ __forceinline__ uint32_t smem_to_u32(const void* p) {
    uint32_t a;
    asm("{ .reg .u64 t; cvta.to.shared.u64 t, %1; cvt.u32.u64 %0, t; }" : "=r"(a) : "l"(p));
    return a;
}

#define LDS128(r0, r1, r2, r3, addr) \
    asm volatile("ld.shared.v4.b32 {%0,%1,%2,%3}, [%4];" \
        : "=r"(r0), "=r"(r1), "=r"(r2), "=r"(r3) : "r"(addr))

#define LDG128(r0, r1, r2, r3, ptr) \
    asm volatile("ld.global.nc.v4.u32 {%0,%1,%2,%3}, [%4];" \
        : "=r"(r0), "=r"(r1), "=r"(r2), "=r"(r3) : "l"(ptr))

#define MMA16816(d, a0, a1, a2, a3, b0, b1) \
    asm volatile("mma.sync.aligned.m16n8k16.row.col.f32.f16.f16.f32 " \
        "{%0,%1,%2,%3}, {%4,%5,%6,%7}, {%8,%9}, {%0,%1,%2,%3};" \
        : "+f"((d)[0]), "+f"((d)[1]), "+f"((d)[2]), "+f"((d)[3]) \
        : "r"(a0), "r"(a1), "r"(a2), "r"(a3), "r"(b0), "r"(b1))

__device__ __forceinline__ void split2(float2 x, uint32_t& h, uint32_t& l) {
    __half2 hp = __float22half2_rn(x);
    float2 hf = __half22float2(hp);
    float2 r = make_float2(x.x - hf.x, x.y - hf.y);
    __half2 lp = __float22half2_rn(r);
    h = *reinterpret_cast<uint32_t*>(&hp);
    l = *reinterpret_cast<uint32_t*>(&lp);
}

// Pack 8 fp32 into hi/lo uint4 chunks (for gmem activation storage).
__device__ __forceinline__ void pack8(const float* v, uint4& hi, uint4& lo) {
    split2(make_float2(v[0], v[1]), hi.x, lo.x);
    split2(make_float2(v[2], v[3]), hi.y, lo.y);
    split2(make_float2(v[4], v[5]), hi.z, lo.z);
    split2(make_float2(v[6], v[7]), hi.w, lo.w);
}
// Pack 8 fp32 into a single hi uint4 (for the SMEM A operand).
__device__ __forceinline__ void pack8_hi(const float* v, uint4& hi) {
    __half2 h0 = __float22half2_rn(make_float2(v[0], v[1]));
    __half2 h1 = __float22half2_rn(make_float2(v[2], v[3]));
    __half2 h2 = __float22half2_rn(make_float2(v[4], v[5]));
    __half2 h3 = __float22half2_rn(make_float2(v[6], v[7]));
    hi.x = *reinterpret_cast<uint32_t*>(&h0);
    hi.y = *reinterpret_cast<uint32_t*>(&h1);
    hi.z = *reinterpret_cast<uint32_t*>(&h2);
    hi.w = *reinterpret_cast<uint32_t*>(&h3);
}
__device__ __forceinline__ void unpack8(uint4 hi, uint4 lo, float* v) {
    const uint32_t* hp = (const uint32_t*)&hi;
    const uint32_t* lp = (const uint32_t*)&lo;
#pragma unroll
    for (int j = 0; j < 4; j++) {
        float2 a = __half22float2(*(const __half2*)&hp[j]);
        float2 b = __half22float2(*(const __half2*)&lp[j]);
        v[2 * j] = a.x + b.x;
        v[2 * j + 1] = a.y + b.y;
    }
}

#define FRAG_OFF(mb, kb, lane) ((size_t)(((mb) * 16 + (kb)) * 32 + (lane)) * 8)

// Load/store a packed activation fragment (gmem tile, hi+lo planes).
__device__ __forceinline__ void load_pack8(const __half* tile, int mb, int kb, int lane,
                                           float* v) {
    size_t off = FRAG_OFF(mb, kb, lane);
    uint4 hi = *(const uint4*)(tile + off);
    uint4 lo = *(const uint4*)(tile + 16384 + off);
    unpack8(hi, lo, v);
}
__device__ __forceinline__ void store_pack8(__half* tile, int mb, int kb, int lane,
                                            const float* v) {
    uint4 hi, lo;
    pack8(v, hi, lo);
    size_t off = FRAG_OFF(mb, kb, lane);
    *(uint4*)(tile + off) = hi;
    *(uint4*)(tile + 16384 + off) = lo;
}

// Write one A fragment chunk to SMEM (hi plane only).
__device__ __forceinline__ void write_A_frag(char* sA, int mb, int kb, int lane,
                                             const float* v) {
    uint4 hi;
    pack8_hi(v, hi);
    uint32_t off = (uint32_t)((mb * 16 + kb) * 32 + lane) * 16;
    *(uint4*)(sA + off) = hi;
}

// ===========================================================================
// prep: pack weights into fragment-order blocks (single fp16 plane).
// ===========================================================================
__device__ __forceinline__ void pack_store(__half* dst, int k, int n, float w) {
    int kb = k >> 4;
    int p = n >> 4;
    int lane = (n & 7) * 4 + ((k >> 1) & 3);
    int idx = ((n >> 3) & 1) * 4 + ((k >> 3) & 1) * 2 + (k & 1);
    size_t off = ((size_t)((kb * 16 + p) * 32 + lane)) * 8 + idx;
    dst[off] = __float2half(w);
}

__global__ void prep_kernel(const float* __restrict__ Wge, const float* __restrict__ Weq,
                            const float* __restrict__ Wtr, const float* __restrict__ Wab,
                            const float* __restrict__ W1,  const float* __restrict__ W2) {
    int i0 = blockIdx.x * 256 + threadIdx.x;
    int stride = gridDim.x * 256;
    for (int i = i0; i < 11 * 65536; i += stride) {
        int blk = i >> 16, e = i & 65535;
        int k = e >> 8, n = e & 255;
        float w;
        __half* dst;
        if (blk == 0)      { w = Weq[k * 256 + n]; dst = WT_eq; }
        else if (blk == 1) { w = Wtr[k * 256 + n]; dst = WT_tr; }
        else if (blk == 2) { w = Wab[k * 256 + n]; dst = WT_ab; }
        else if (blk <= 4) { int h = blk - 3; w = Wge[(k + h * 256) * 256 + n]; dst = WT_ge + (size_t)h * BLK_STRIDE; }
        else if (blk <= 6) { int h = blk - 5; w = W1 [(k + h * 256) * 256 + n]; dst = WT_1  + (size_t)h * BLK_STRIDE; }
        else               { int t = blk - 7; int ng = t * 256 + n;
                             w = (ng < 1000) ? W2[k * 1000 + ng] : 0.0f;
                             dst = WT_2 + (size_t)t * BLK_STRIDE; }
        pack_store(dst, k, n, w);
    }
}

// ===========================================================================
// HMMA GEMM core: single product (fp16 A hi-plane x fp16 B). 16 MMAs/kc/warp.
// 8 warps, wn = warp id; warp tile m64 x n32. B register double-buffered.
// ===========================================================================
__device__ __forceinline__ void hmma_gemm_k256(uint32_t sA,
                                               const __half* __restrict__ blk,
                                               float acc[4][4][4],
                                               int tid, bool zero_acc) {
    if (zero_acc) {
#pragma unroll
        for (int mt = 0; mt < 4; mt++)
#pragma unroll
            for (int nt = 0; nt < 4; nt++)
#pragma unroll
                for (int i = 0; i < 4; i++) acc[mt][nt][i] = 0.f;
    }
    const int lane = tid & 31;
    const int wn = tid >> 5;
    const uint32_t abase = sA + (uint32_t)(lane * 16);
    const __half* bbase = blk + ((size_t)(wn * 2) * 32 + lane) * 8;

    uint32_t bh[2][2][4];
#pragma unroll
    for (int pp = 0; pp < 2; pp++) {
        const __half* bp = bbase + pp * 256;
        LDG128(bh[0][pp][0], bh[0][pp][1], bh[0][pp][2], bh[0][pp][3], bp);
    }

    __syncthreads();   // A fragments visible

#pragma unroll 4
    for (int kc = 0; kc < 16; kc++) {
        const int cur = kc & 1, nxt = cur ^ 1;
        if (kc < 15) {
            const __half* bk = bbase + (size_t)(kc + 1) * 4096;
#pragma unroll
            for (int pp = 0; pp < 2; pp++) {
                const __half* bp = bk + pp * 256;
                LDG128(bh[nxt][pp][0], bh[nxt][pp][1], bh[nxt][pp][2], bh[nxt][pp][3], bp);
            }
        }
        uint32_t ah[4][4];
#pragma unroll
        for (int mt = 0; mt < 4; mt++) {
            uint32_t aaddr = abase + (uint32_t)(mt * 8192 + kc * 512);
            LDS128(ah[mt][0], ah[mt][1], ah[mt][2], ah[mt][3], aaddr);
        }
#pragma unroll
        for (int pp = 0; pp < 2; pp++) {
#pragma unroll
            for (int mt = 0; mt < 4; mt++) {
                MMA16816(acc[mt][2 * pp], ah[mt][0], ah[mt][1], ah[mt][2], ah[mt][3],
                         bh[cur][pp][0], bh[cur][pp][1]);
                MMA16816(acc[mt][2 * pp + 1], ah[mt][0], ah[mt][1], ah[mt][2], ah[mt][3],
                         bh[cur][pp][2], bh[cur][pp][3]);
            }
        }
    }
    __syncthreads();   // all A reads done before caller rewrites A
}

// Fill SMEM A (hi plane) from a packed gmem tile: straight 32KB copy.
__device__ __forceinline__ void fill_A_packed(char* sA, const __half* __restrict__ tile,
                                              int tid) {
#pragma unroll
    for (int i = 0; i < 8; i++) {
        int idx = i * NTHREADS + tid;            // 0..2047 (hi plane chunks)
        uint4 v = *(const uint4*)(tile + (size_t)idx * 8);
        *(uint4*)(sA + (size_t)idx * 16) = v;
    }
}

// Fill SMEM A (hi plane) from fp32 row-major gmem (encoder input x only).
__device__ __forceinline__ void fill_A_f32(char* sA, const float* __restrict__ src,
                                           int ld, int tid) {
#pragma unroll
    for (int i = 0; i < 8; i++) {
        int idx = i * NTHREADS + tid;
        int mb = idx >> 9, kb = (idx >> 5) & 15, ln = idx & 31;
        int gid = ln >> 2, qid = ln & 3;
        const float* p0 = src + (size_t)(mb * 16 + gid) * ld + kb * 16 + 2 * qid;
        float v[8];
        float2 x0 = *(const float2*)(p0);
        float2 x1 = *(const float2*)(p0 + 8 * (size_t)ld);
        float2 x2 = *(const float2*)(p0 + 8);
        float2 x3 = *(const float2*)(p0 + 8 * (size_t)ld + 8);
        v[0] = x0.x; v[1] = x0.y; v[2] = x1.x; v[3] = x1.y;
        v[4] = x2.x; v[5] = x2.y; v[6] = x3.x; v[7] = x3.y;
        write_A_frag(sA, mb, kb, ln, v);
    }
}

#define FRAG_SETUP() \
    const int lane = tid & 31; \
    const int wn = tid >> 5; \
    const int gid = lane >> 2, qid = lane & 3;

// ===========================================================================
// Fused plate kernel: packed activation tiles. 64 rows/CTA, 2 CTAs/SM.
// ===========================================================================
template <bool DESC>
__global__ __launch_bounds__(NTHREADS, 2) void plate_hmma(
    const __half* __restrict__ g_in, const __half* __restrict__ l_in,
    __half* __restrict__ out,
    const float* __restrict__ b_eq, const float* __restrict__ b_tr,
    const float* __restrict__ b_ab, const float* __restrict__ alpha_p) {
    extern __shared__ char sm[];
    char* sA_p = sm;
    uint32_t sA = smem_to_u32(sm);
    const int tid = threadIdx.x;
    const size_t tb = blockIdx.x;
    const __half* gt = g_in + tb * TILE_HALFS;
    const __half* lt = l_in + tb * TILE_HALFS;
    __half* ot = out + tb * TILE_HALFS;
    FRAG_SETUP();

    fill_A_packed(sA_p, lt, tid);

    float acc[4][4][4];
    hmma_gemm_k256(sA, WT_eq, acc, tid, true);

    // Epilogue 1: df = g - sigmoid(acc + b_eq) -> A hi plane
#pragma unroll
    for (int mt = 0; mt < 4; mt++) {
#pragma unroll
        for (int ntp = 0; ntp < 2; ntp++) {
            int kbf = wn * 2 + ntp;
            int ce = wn * 32 + ntp * 16 + qid * 2;
            float2 beE = *(const float2*)(b_eq + ce);
            float2 beO = *(const float2*)(b_eq + ce + 8);
            float gv[8], v[8];
            load_pack8(gt, mt, kbf, lane, gv);
            const float* aE = acc[mt][2 * ntp];
            const float* aO = acc[mt][2 * ntp + 1];
            v[0] = gv[0] - sigm(aE[0] + beE.x);
            v[1] = gv[1] - sigm(aE[1] + beE.y);
            v[2] = gv[2] - sigm(aE[2] + beE.x);
            v[3] = gv[3] - sigm(aE[3] + beE.y);
            v[4] = gv[4] - sigm(aO[0] + beO.x);
            v[5] = gv[5] - sigm(aO[1] + beO.y);
            v[6] = gv[6] - sigm(aO[2] + beO.x);
            v[7] = gv[7] - sigm(aO[3] + beO.y);
            write_A_frag(sA_p, mt, kbf, lane, v);
        }
    }

    hmma_gemm_k256(sA, WT_tr, acc, tid, true);

    const float alpha = *alpha_p;

    if (!DESC) {
        // out = g - alpha*(acc + b_tr), packed hi/lo
#pragma unroll
        for (int mt = 0; mt < 4; mt++) {
#pragma unroll
            for (int ntp = 0; ntp < 2; ntp++) {
                int kbf = wn * 2 + ntp;
                int ce = wn * 32 + ntp * 16 + qid * 2;
                float2 btE = *(const float2*)(b_tr + ce);
                float2 btO = *(const float2*)(b_tr + ce + 8);
                float gv[8], v[8];
                load_pack8(gt, mt, kbf, lane, gv);
                const float* aE = acc[mt][2 * ntp];
                const float* aO = acc[mt][2 * ntp + 1];
                v[0] = gv[0] - alpha * (aE[0] + btE.x);
                v[1] = gv[1] - alpha * (aE[1] + btE.y);
                v[2] = gv[2] - alpha * (aE[2] + btE.x);
                v[3] = gv[3] - alpha * (aE[3] + btE.y);
                v[4] = gv[4] - alpha * (aO[0] + btO.x);
                v[5] = gv[5] - alpha * (aO[1] + btO.y);
                v[6] = gv[6] - alpha * (aO[2] + btO.x);
                v[7] = gv[7] - alpha * (aO[3] + btO.y);
                store_pack8(ot, mt, kbf, lane, v);
            }
        }
    } else {
        // delta = alpha*(acc + b_tr) -> A hi plane
#pragma unroll
        for (int mt = 0; mt < 4; mt++) {
#pragma unroll
            for (int ntp = 0; ntp < 2; ntp++) {
                int kbf = wn * 2 + ntp;
                int ce = wn * 32 + ntp * 16 + qid * 2;
                float2 btE = *(const float2*)(b_tr + ce);
                float2 btO = *(const float2*)(b_tr + ce + 8);
                float v[8];
                const float* aE = acc[mt][2 * ntp];
                const float* aO = acc[mt][2 * ntp + 1];
                v[0] = alpha * (aE[0] + btE.x);
                v[1] = alpha * (aE[1] + btE.y);
                v[2] = alpha * (aE[2] + btE.x);
                v[3] = alpha * (aE[3] + btE.y);
                v[4] = alpha * (aO[0] + btO.x);
                v[5] = alpha * (aO[1] + btO.y);
                v[6] = alpha * (aO[2] + btO.x);
                v[7] = alpha * (aO[3] + btO.y);
                write_A_frag(sA_p, mt, kbf, lane, v);
            }
        }

        hmma_gemm_k256(sA, WT_ab, acc, tid, true);

        // out = l + acc + b_ab, packed hi/lo
#pragma unroll
        for (int mt = 0; mt < 4; mt++) {
#pragma unroll
            for (int ntp = 0; ntp < 2; ntp++) {
                int kbf = wn * 2 + ntp;
                int ce = wn * 32 + ntp * 16 + qid * 2;
                float2 baE = *(const float2*)(b_ab + ce);
                float2 baO = *(const float2*)(b_ab + ce + 8);
                float lv[8], v[8];
                load_pack8(lt, mt, kbf, lane, lv);
                const float* aE = acc[mt][2 * ntp];
                const float* aO = acc[mt][2 * ntp + 1];
                v[0] = lv[0] + aE[0] + baE.x;
                v[1] = lv[1] + aE[1] + baE.y;
                v[2] = lv[2] + aE[2] + baE.x;
                v[3] = lv[3] + aE[3] + baE.y;
                v[4] = lv[4] + aO[0] + baO.x;
                v[5] = lv[5] + aO[1] + baO.y;
                v[6] = lv[6] + aO[2] + baO.x;
                v[7] = lv[7] + aO[3] + baO.y;
                store_pack8(ot, mt, kbf, lane, v);
            }
        }
    }
}

// ===========================================================================
// Encoder: g0 = relu(x @ W_ge + b_ge) -> packed tile
// ===========================================================================
__global__ __launch_bounds__(NTHREADS, 2) void encoder_hmma(
    const float* __restrict__ x, const float* __restrict__ b_ge,
    __half* __restrict__ g0) {
    extern __shared__ char sm[];
    char* sA_p = sm;
    uint32_t sA = smem_to_u32(sm);
    const int tid = threadIdx.x;
    const size_t tb = blockIdx.x;
    const size_t rowbase = tb * MTILE;
    __half* g0t = g0 + tb * TILE_HALFS;
    FRAG_SETUP();

    float acc[4][4][4];
    fill_A_f32(sA_p, x + rowbase * 512, 512, tid);
    hmma_gemm_k256(sA, WT_ge, acc, tid, true);
    fill_A_f32(sA_p, x + rowbase * 512 + 256, 512, tid);
    hmma_gemm_k256(sA, WT_ge + BLK_STRIDE, acc, tid, false);

#pragma unroll
    for (int mt = 0; mt < 4; mt++) {
#pragma unroll
        for (int ntp = 0; ntp < 2; ntp++) {
            int kbf = wn * 2 + ntp;
            int ce = wn * 32 + ntp * 16 + qid * 2;
            float2 bE = *(const float2*)(b_ge + ce);
            float2 bO = *(const float2*)(b_ge + ce + 8);
            float v[8];
            const float* aE = acc[mt][2 * ntp];
            const float* aO = acc[mt][2 * ntp + 1];
            v[0] = fmaxf(aE[0] + bE.x, 0.f);
            v[1] = fmaxf(aE[1] + bE.y, 0.f);
            v[2] = fmaxf(aE[2] + bE.x, 0.f);
            v[3] = fmaxf(aE[3] + bE.y, 0.f);
            v[4] = fmaxf(aO[0] + bO.x, 0.f);
            v[5] = fmaxf(aO[1] + bO.y, 0.f);
            v[6] = fmaxf(aO[2] + bO.x, 0.f);
            v[7] = fmaxf(aO[3] + bO.y, 0.f);
            store_pack8(g0t, mt, kbf, lane, v);
        }
    }
}

// ===========================================================================
// Head: h = relu([g8||l1] @ W1 + b1); out = h @ W2 + b2  (fp32 output)
// ===========================================================================
__global__ __launch_bounds__(NTHREADS, 2) void head_hmma(
    const __half* __restrict__ g8, const __half* __restrict__ l1,
    const float* __restrict__ b1, const float* __restrict__ b2,
    float* __restrict__ out) {
    extern __shared__ char sm[];
    char* sA_p = sm;
    uint32_t sA = smem_to_u32(sm);
    const int tid = threadIdx.x;
    const size_t tb = blockIdx.x;
    const size_t rowbase = tb * MTILE;
    FRAG_SETUP();

    float acc[4][4][4];
    fill_A_packed(sA_p, g8 + tb * TILE_HALFS, tid);
    hmma_gemm_k256(sA, WT_1, acc, tid, true);
    fill_A_packed(sA_p, l1 + tb * TILE_HALFS, tid);
    hmma_gemm_k256(sA, WT_1 + BLK_STRIDE, acc, tid, false);

    // h = relu(acc + b1) -> A hi plane
#pragma unroll
    for (int mt = 0; mt < 4; mt++) {
#pragma unroll
        for (int ntp = 0; ntp < 2; ntp++) {
            int kbf = wn * 2 + ntp;
            int ce = wn * 32 + ntp * 16 + qid * 2;
            float2 bE = *(const float2*)(b1 + ce);
            float2 bO = *(const float2*)(b1 + ce + 8);
            float v[8];
            const float* aE = acc[mt][2 * ntp];
            const float* aO = acc[mt][2 * ntp + 1];
            v[0] = fmaxf(aE[0] + bE.x, 0.f);
            v[1] = fmaxf(aE[1] + bE.y, 0.f);
            v[2] = fmaxf(aE[2] + bE.x, 0.f);
            v[3] = fmaxf(aE[3] + bE.y, 0.f);
            v[4] = fmaxf(aO[0] + bO.x, 0.f);
            v[5] = fmaxf(aO[1] + bO.y, 0.f);
            v[6] = fmaxf(aO[2] + bO.x, 0.f);
            v[7] = fmaxf(aO[3] + bO.y, 0.f);
            write_A_frag(sA_p, mt, kbf, lane, v);
        }
    }

    for (int t = 0; t < 4; t++) {
        hmma_gemm_k256(sA, WT_2 + (size_t)t * BLK_STRIDE, acc, tid, true);
#pragma unroll
        for (int mt = 0; mt < 4; mt++) {
#pragma unroll
            for (int nt = 0; nt < 4; nt++) {
                int col = t * 256 + wn * 32 + (nt >> 1) * 16 + (nt & 1) * 8 + qid * 2;
                if (col < 1000) {
                    int r = mt * 16 + gid;
                    size_t ro = (rowbase + r) * 1000 + col;
                    float2 b = *(const float2*)(b2 + col);
                    float2 o0, o1;
                    o0.x = acc[mt][nt][0] + b.x;
                    o0.y = acc[mt][nt][1] + b.y;
                    o1.x = acc[mt][nt][2] + b.x;
                    o1.y = acc[mt][nt][3] + b.y;
                    *(float2*)(out + ro) = o0;
                    *(float2*)(out + ro + 8 * 1000) = o1;
                }
            }
        }
    }
}

// ===========================================================================
extern "C" void kernel_launch(void* const* d_in, const int* in_sizes, int n_in,
                              void* d_out, int out_size) {
    (void)in_sizes; (void)n_in; (void)out_size;
    const float* x     = (const float*)d_in[0];
    const float* W_ge  = (const float*)d_in[1];
    const float* b_ge  = (const float*)d_in[2];
    const float* W_eq  = (const float*)d_in[3];
    const float* b_eq  = (const float*)d_in[4];
    const float* W_tr  = (const float*)d_in[5];
    const float* b_tr  = (const float*)d_in[6];
    const float* W_ab  = (const float*)d_in[7];
    const float* b_ab  = (const float*)d_in[8];
    const float* alpha = (const float*)d_in[9];
    const float* W1    = (const float*)d_in[10];
    const float* b1    = (const float*)d_in[11];
    const float* W2    = (const float*)d_in[12];
    const float* b2    = (const float*)d_in[13];
    float* out = (float*)d_out;

    __half *gb = nullptr, *lb = nullptr;
    cudaGetSymbolAddress((void**)&gb, g_bufs);
    cudaGetSymbolAddress((void**)&lb, l_bufs);
    auto G = [&](int i) { return gb + (size_t)i * NTILES * TILE_HALFS; };
    auto L = [&](int i) { return lb + (size_t)i * NTILES * TILE_HALFS; };

    cudaFuncSetAttribute(plate_hmma<true>,  cudaFuncAttributeMaxDynamicSharedMemorySize, SMEM_TOTAL);
    cudaFuncSetAttribute(plate_hmma<false>, cudaFuncAttributeMaxDynamicSharedMemorySize, SMEM_TOTAL);
    cudaFuncSetAttribute(encoder_hmma,      cudaFuncAttributeMaxDynamicSharedMemorySize, SMEM_TOTAL);
    cudaFuncSetAttribute(head_hmma,         cudaFuncAttributeMaxDynamicSharedMemorySize, SMEM_TOTAL);

    cudaMemsetAsync(L(9), 0, (size_t)NTILES * TILE_HALFS * sizeof(__half));
    prep_kernel<<<512, 256>>>(W_ge, W_eq, W_tr, W_ab, W1, W2);

    dim3 grid(NTILES);   // 256 CTAs, 2 CTAs/SM

    encoder_hmma<<<grid, NTHREADS, SMEM_TOTAL>>>(x, b_ge, G(0));

    // Sweep 1: descending (g[1..8] None -> g_in = g0)
    for (int n = 8; n >= 1; --n)
        plate_hmma<true><<<grid, NTHREADS, SMEM_TOTAL>>>(G(0), L(n + 1), L(n),
                                                         b_eq, b_tr, b_ab, alpha);
    // Sweep 1: ascending
    for (int n = 1; n <= 8; ++n)
        plate_hmma<false><<<grid, NTHREADS, SMEM_TOTAL>>>(G(n - 1), L(n), G(n),
                                                          b_eq, b_tr, b_ab, alpha);
    // Sweep 2: descending
    for (int n = 8; n >= 1; --n)
        plate_hmma<true><<<grid, NTHREADS, SMEM_TOTAL>>>(G(n - 1), L(n + 1), L(n),
                                                         b_eq, b_tr, b_ab, alpha);
    // Sweep 2: ascending
    for (int n = 1; n <= 8; ++n)
        plate_hmma<false><<<grid, NTHREADS, SMEM_TOTAL>>>(G(n - 1), L(n), G(n),
                                                          b_eq, b_tr, b_ab, alpha);

    head_hmma<<<grid, NTHREADS, SMEM_TOTAL>>>(G(8), L(1), b1, b2, out);
}